// round 8
// baseline (speedup 1.0000x reference)
#include <cuda_runtime.h>
#include <cuda_fp16.h>
#include <math.h>
#include <stdint.h>

// ---------------------------------------------------------------------------
// RankingCNN: conv(s32,k32) == GEMM C[3072,1568] = Wb[3072,3072] @ P[3072,1568]
// fp32 via fp16 split on legacy tensor cores (mma.sync.m16n8k16):
//   C = Ah*Bh (fp32 acc) + [Ah*Bl + Al*Bh] (fp16 acc, merged at end)
// R8: warp tile 64x32 (4 warps/CTA, 128 thr) -> 2.7x less smem fragment
// traffic per flop; CTA tile 64x128 keeps 624-CTA wave smoothness.
// ---------------------------------------------------------------------------

#define NBR 3
#define BATCH 32
#define KDIM 3072
#define MDIM 3072
#define NDIM 1568
#define NPAD 1664            // 13 * 128; pad rows stay zero (static init)
#define RANK_OFF 0
#define CAM_OFF 96
#define FEAT_OFF 9504
#define FPB 1605632
#define FPI 50176

#define BM 64
#define BN 128
#define BK 32
#define NC (KDIM / BK)       // 96 k-chunks

// rows are 64B (32 fp16); swizzle: 16B-chunk index ^= (row>>1)&3
#define A_T 4096             // one A tile (64 x 64B)
#define B_T 8192             // one B tile (128 x 64B)
#define STAGE_B 24576        // Ah | Al | Bh | Bl
#define NSTAGE 4
#define SMEM_DYN (NSTAGE * STAGE_B)   // 98304

// ---- static scratch (no allocations allowed) ------------------------------
__device__ __align__(256) __half g_Ah[MDIM * KDIM];
__device__ __align__(256) __half g_Al[MDIM * KDIM];
__device__ __align__(256) __half g_Bh[NPAD * KDIM];   // pad rows never written -> 0
__device__ __align__(256) __half g_Bl[NPAD * KDIM];
__device__ float g_pooled[NBR * BATCH * 1024];
__device__ float g_h[NBR * BATCH * 512];

// ---- PTX helpers ----------------------------------------------------------
__device__ __forceinline__ uint32_t smem_u32(const void* p) {
    uint32_t a;
    asm("{ .reg .u64 t; cvta.to.shared.u64 t, %1; cvt.u32.u64 %0, t; }" : "=r"(a) : "l"(p));
    return a;
}
__device__ __forceinline__ void cp16(uint32_t dst, const void* src) {
    asm volatile("cp.async.cg.shared.global [%0], [%1], 16;" :: "r"(dst), "l"(src));
}
__device__ __forceinline__ void ldmx4(uint32_t* r, uint32_t a) {
    asm volatile("ldmatrix.sync.aligned.m8n8.x4.shared.b16 {%0,%1,%2,%3}, [%4];"
        : "=r"(r[0]), "=r"(r[1]), "=r"(r[2]), "=r"(r[3]) : "r"(a));
}
__device__ __forceinline__ void mma16816(float* c, const uint32_t* a, const uint32_t* b) {
    asm volatile("mma.sync.aligned.m16n8k16.row.col.f32.f16.f16.f32 "
        "{%0,%1,%2,%3}, {%4,%5,%6,%7}, {%8,%9}, {%0,%1,%2,%3};"
        : "+f"(c[0]), "+f"(c[1]), "+f"(c[2]), "+f"(c[3])
        : "r"(a[0]), "r"(a[1]), "r"(a[2]), "r"(a[3]), "r"(b[0]), "r"(b[1]));
}
__device__ __forceinline__ void mma16816h(uint32_t* c, const uint32_t* a, const uint32_t* b) {
    asm volatile("mma.sync.aligned.m16n8k16.row.col.f16.f16.f16.f16 "
        "{%0,%1}, {%2,%3,%4,%5}, {%6,%7}, {%0,%1};"
        : "+r"(c[0]), "+r"(c[1])
        : "r"(a[0]), "r"(a[1]), "r"(a[2]), "r"(a[3]), "r"(b[0]), "r"(b[1]));
}

// ---------------------------------------------------------------------------
// Kernel 0: no-op spacer (shifts the ncu capture slot onto the GEMM)
// ---------------------------------------------------------------------------
__global__ void noop_kernel() {}

// ---------------------------------------------------------------------------
// Kernel 1: Wb fp32 -> fp16 (hi, lo)
// ---------------------------------------------------------------------------
__global__ __launch_bounds__(256) void conv_a_kernel(const float* __restrict__ Wb) {
    int i2 = (blockIdx.x * 256 + threadIdx.x) * 2;
    if (i2 >= MDIM * KDIM) return;
    float2 v = *(const float2*)(Wb + i2);
    __half h0 = __float2half(v.x), h1 = __float2half(v.y);
    __half l0 = __float2half(v.x - __half2float(h0));
    __half l1 = __float2half(v.y - __half2float(h1));
    *(__half2*)(g_Ah + i2) = __half2(h0, h1);
    *(__half2*)(g_Al + i2) = __half2(l0, l1);
}

// ---------------------------------------------------------------------------
// Kernel 2: fused im2col + fp16 split: Bt[n][k], k = c*1024 + kh*32 + kw
// ---------------------------------------------------------------------------
__global__ __launch_bounds__(256) void im2col_kernel(const float* __restrict__ x) {
    int i2 = (blockIdx.x * 256 + threadIdx.x) * 2;
    if (i2 >= NDIM * KDIM) return;
    int n = i2 / KDIM;
    int k = i2 - n * KDIM;          // even
    int c = k >> 10, r = k & 1023, kh = r >> 5, kw = r & 31;
    int b = n / 49, t = n - b * 49, ii = t / 7, jj = t - ii * 7;
    const float* src = x + ((size_t)(b * 3 + c) * 224 + ii * 32 + kh) * 224 + jj * 32 + kw;
    float2 v = *(const float2*)src;
    __half h0 = __float2half(v.x), h1 = __float2half(v.y);
    __half l0 = __float2half(v.x - __half2float(h0));
    __half l1 = __float2half(v.y - __half2float(h1));
    *(__half2*)(g_Bh + i2) = __half2(h0, h1);
    *(__half2*)(g_Bl + i2) = __half2(l0, l1);
}

// ---------------------------------------------------------------------------
// Kernel 3: GEMM 64x128x32 per CTA, 4 warps of 64x32 (1m x 4n), 4 stages
// ---------------------------------------------------------------------------
__global__ __launch_bounds__(128, 2) void gemm_mma_kernel(const float* __restrict__ bias,
                                                          float* __restrict__ out) {
    extern __shared__ char smem[];
    const uint32_t s0 = smem_u32(smem);

    const int tid = threadIdx.x;
    const int wid = tid >> 5;          // 0..3  (n quarter)
    const int lane = tid & 31;
    const int mBase = blockIdx.y * BM;
    const int nBase = blockIdx.x * BN;

    // ---- cp.async mapping: 128 thr; thread -> row r = tid>>2, chunk = tid&3
    const int c = tid & 3;
    const int r = tid >> 2;                     // 0..31
    const uint32_t cSw = (uint32_t)((c ^ ((r >> 1) & 3)) << 4);  // same for r+32k
    const uint32_t rOff = (uint32_t)(r * 64) + cSw;
    const __half* gAh = g_Ah + (size_t)(mBase + r) * KDIM + c * 8;
    const __half* gAl = g_Al + (size_t)(mBase + r) * KDIM + c * 8;
    const __half* gBh = g_Bh + (size_t)(nBase + r) * KDIM + c * 8;
    const __half* gBl = g_Bl + (size_t)(nBase + r) * KDIM + c * 8;
    const size_t j32 = (size_t)32 * KDIM;

#define ISSUE(kt) do {                                                          \
        const uint32_t st = s0 + (uint32_t)(((kt) & 3) * STAGE_B);              \
        const int k0 = (kt) * BK;                                               \
        cp16(st + rOff,                 gAh + k0);                              \
        cp16(st + rOff + 2048,          gAh + j32 + k0);                        \
        cp16(st + A_T + rOff,           gAl + k0);                              \
        cp16(st + A_T + rOff + 2048,    gAl + j32 + k0);                        \
        cp16(st + 2*A_T + rOff,         gBh + k0);                              \
        cp16(st + 2*A_T + rOff + 2048,  gBh + j32 + k0);                        \
        cp16(st + 2*A_T + rOff + 4096,  gBh + 2*j32 + k0);                      \
        cp16(st + 2*A_T + rOff + 6144,  gBh + 3*j32 + k0);                      \
        cp16(st + 2*A_T + B_T + rOff,        gBl + k0);                         \
        cp16(st + 2*A_T + B_T + rOff + 2048, gBl + j32 + k0);                   \
        cp16(st + 2*A_T + B_T + rOff + 4096, gBl + 2*j32 + k0);                 \
        cp16(st + 2*A_T + B_T + rOff + 6144, gBl + 3*j32 + k0);                 \
        asm volatile("cp.async.commit_group;");                                 \
    } while (0)

    // ---- accumulators (warp tile 64x32: mf 0..3, nf 0..3) ------------------
    float acc[4][4][4];
    uint32_t acch[4][4][2];
#pragma unroll
    for (int i = 0; i < 4; i++)
#pragma unroll
        for (int j = 0; j < 4; j++) {
#pragma unroll
            for (int q = 0; q < 4; q++) acc[i][j][q] = 0.f;
            acch[i][j][0] = 0u; acch[i][j][1] = 0u;
        }

    // ---- ldmatrix addressing ----------------------------------------------
    // A x4: row = mf*16 + (lane&15); chunk = ks*2 + (lane>>4)
    const int aR = lane & 15;
    const int aHi = lane >> 4;
    // B x4 (pair of nf): row = wid*32 + p*16 + ((lane>>4)<<3) + (lane&7)
    //                    chunk = ks*2 + ((lane>>3)&1)
    const int bR = wid * 32 + ((lane >> 4) << 3) + (lane & 7);
    const int bHi = (lane >> 3) & 1;

    ISSUE(0); ISSUE(1); ISSUE(2);

    for (int kt = 0; kt < NC; kt++) {
        asm volatile("cp.async.wait_group 2;");
        __syncthreads();
        if (kt + 3 < NC) ISSUE(kt + 3);
        else asm volatile("cp.async.commit_group;");

        const uint32_t sb = s0 + (uint32_t)((kt & 3) * STAGE_B);

#pragma unroll
        for (int ks = 0; ks < 2; ks++) {
            uint32_t ah[4][4], al[4][4], bh[4][2], bl[4][2];
#pragma unroll
            for (int mf = 0; mf < 4; mf++) {
                const int row = aR + mf * 16;
                const uint32_t ad = sb + (uint32_t)(row * 64)
                    + (uint32_t)(((ks * 2 + aHi) ^ ((row >> 1) & 3)) << 4);
                ldmx4(ah[mf], ad);
                ldmx4(al[mf], ad + A_T);
            }
#pragma unroll
            for (int p = 0; p < 2; p++) {
                const int row = bR + p * 16;
                const uint32_t bd = sb + 2 * A_T + (uint32_t)(row * 64)
                    + (uint32_t)(((ks * 2 + bHi) ^ ((row >> 1) & 3)) << 4);
                uint32_t t[4];
                ldmx4(t, bd);
                bh[2*p][0] = t[0]; bh[2*p][1] = t[1];
                bh[2*p+1][0] = t[2]; bh[2*p+1][1] = t[3];
                ldmx4(t, bd + B_T);
                bl[2*p][0] = t[0]; bl[2*p][1] = t[1];
                bl[2*p+1][0] = t[2]; bl[2*p+1][1] = t[3];
            }
#pragma unroll
            for (int mf = 0; mf < 4; mf++)
#pragma unroll
                for (int nf = 0; nf < 4; nf++) {
                    mma16816(acc[mf][nf], ah[mf], bh[nf]);
                    mma16816h(acch[mf][nf], ah[mf], bl[nf]);
                    mma16816h(acch[mf][nf], al[mf], bh[nf]);
                }
        }
    }

    // ---- merge fp16 accumulators, bias, scatter to feature layout ----------
#pragma unroll
    for (int mf = 0; mf < 4; mf++) {
        const int m0 = mBase + mf * 16 + (lane >> 2);
        const int m1 = m0 + 8;
        const float bv0 = bias[m0], bv1 = bias[m1];
        float* ob0 = out + FEAT_OFF + (size_t)(m0 >> 10) * FPB + (size_t)(m0 & 1023) * 49;
        float* ob1 = out + FEAT_OFF + (size_t)(m1 >> 10) * FPB + (size_t)(m1 & 1023) * 49;
#pragma unroll
        for (int nf = 0; nf < 4; nf++) {
            const int n = nBase + wid * 32 + nf * 8 + (lane & 3) * 2;
            __half2 lo01 = *(__half2*)&acch[mf][nf][0];
            __half2 lo23 = *(__half2*)&acch[mf][nf][1];
            float v0 = acc[mf][nf][0] + __low2float(lo01);
            float v1 = acc[mf][nf][1] + __high2float(lo01);
            float v2 = acc[mf][nf][2] + __low2float(lo23);
            float v3 = acc[mf][nf][3] + __high2float(lo23);
            if (n < NDIM) {
                int b0 = n / 49,       sA = n - b0 * 49;
                int b1 = (n + 1) / 49, sB = (n + 1) - b1 * 49;
                ob0[(size_t)b0 * FPI + sA] = v0 + bv0;
                ob0[(size_t)b1 * FPI + sB] = v1 + bv0;
                ob1[(size_t)b0 * FPI + sA] = v2 + bv1;
                ob1[(size_t)b1 * FPI + sB] = v3 + bv1;
            }
        }
    }
#undef ISSUE
}

// ---------------------------------------------------------------------------
// Kernel 4: global average pool -> g_pooled[n][b][1024]  (grid 96 x 4)
// ---------------------------------------------------------------------------
__global__ __launch_bounds__(256) void gap_kernel(const float* __restrict__ out) {
    const int n = blockIdx.x >> 5, b = blockIdx.x & 31;
    const int ch = blockIdx.y * 256 + threadIdx.x;
    const float* fo = out + FEAT_OFF + (size_t)n * FPB + (size_t)b * FPI + (size_t)ch * 49;
    float s = 0.f;
#pragma unroll
    for (int q = 0; q < 49; q++) s += fo[q];
    g_pooled[(n * 32 + b) * 1024 + ch] = s * (1.0f / 49.0f);
}

// ---------------------------------------------------------------------------
// Kernel 5: Linear(1024,512)+ReLU, weight-streamed
// ---------------------------------------------------------------------------
__global__ __launch_bounds__(256) void mlp1_kernel(const float* __restrict__ p1w,
                                                   const float* __restrict__ p1b) {
    const int branch = blockIdx.y;
    const int wid = threadIdx.x >> 5, lane = threadIdx.x & 31;
    const int j = blockIdx.x * 8 + wid;
    const float* w = p1w + (size_t)(branch * 512 + j) * 1024;
    float wr[32];
#pragma unroll
    for (int t = 0; t < 32; t++) wr[t] = w[t * 32 + lane];
    const float bj = p1b[branch * 512 + j];
    for (int b = 0; b < 32; b++) {
        const float* pp = g_pooled + (branch * 32 + b) * 1024;
        float s = 0.f;
#pragma unroll
        for (int t = 0; t < 32; t++) s = fmaf(wr[t], pp[t * 32 + lane], s);
#pragma unroll
        for (int off = 16; off; off >>= 1) s += __shfl_xor_sync(0xffffffffu, s, off);
        if (lane == 0) g_h[(branch * 32 + b) * 512 + j] = fmaxf(s + bj, 0.f);
    }
}

// ---------------------------------------------------------------------------
// Kernel 6: Linear(512,2) + softmax[:,1] -> ranking
// ---------------------------------------------------------------------------
__global__ __launch_bounds__(256) void mlp2_kernel(const float* __restrict__ p2w,
                                                   const float* __restrict__ p2b,
                                                   float* __restrict__ out) {
    const int branch = blockIdx.x;
    const int wid = threadIdx.x >> 5, lane = threadIdx.x & 31;
    const float* w0 = p2w + branch * 1024;
    const float* w1 = w0 + 512;
    for (int b = wid; b < 32; b += 8) {
        const float* h = g_h + (branch * 32 + b) * 512;
        float s0 = 0.f, s1 = 0.f;
        for (int t = lane; t < 512; t += 32) {
            float hv = h[t];
            s0 = fmaf(hv, w0[t], s0);
            s1 = fmaf(hv, w1[t], s1);
        }
#pragma unroll
        for (int off = 16; off; off >>= 1) {
            s0 += __shfl_xor_sync(0xffffffffu, s0, off);
            s1 += __shfl_xor_sync(0xffffffffu, s1, off);
        }
        if (lane == 0) {
            float l0 = s0 + p2b[branch * 2 + 0];
            float l1 = s1 + p2b[branch * 2 + 1];
            float mx = fmaxf(l0, l1);
            float e0 = expf(l0 - mx), e1 = expf(l1 - mx);
            out[RANK_OFF + b * 3 + branch] = e1 / (e0 + e1);
        }
    }
}

// ---------------------------------------------------------------------------
// Kernel 7: CAM — 98 dot-products of length 1024 per (branch,image)
// ---------------------------------------------------------------------------
__global__ __launch_bounds__(256) void cam_kernel(const float* __restrict__ out_r,
                                                  const float* __restrict__ clsw,
                                                  float* __restrict__ out_w) {
    __shared__ float wts[2048];
    __shared__ float tile[128 * 49];
    const int n = blockIdx.x >> 5, b = blockIdx.x & 31;
    const int tid = threadIdx.x, w = tid >> 5, lane = tid & 31;
    const float* f = out_r + FEAT_OFF + (size_t)n * FPB + (size_t)b * FPI;

    for (int i = tid; i < 2048; i += 256) wts[i] = clsw[n * 2048 + i];

    const int nd = (w < 2) ? 13 : 12;
    float acc[13];
#pragma unroll
    for (int i = 0; i < 13; i++) acc[i] = 0.f;

    for (int ch = 0; ch < 8; ch++) {
        __syncthreads();
        for (int i = tid; i < 128 * 49; i += 256) tile[i] = f[ch * (128 * 49) + i];
        __syncthreads();
#pragma unroll
        for (int di = 0; di < 13; di++) {
            if (di >= nd) break;
            int d = w + di * 8;
            int cls = d / 49, s = d - cls * 49;
            const float* wp = wts + cls * 1024 + ch * 128;
            float a = acc[di];
#pragma unroll
            for (int o4 = 0; o4 < 4; o4++)
                a = fmaf(wp[o4 * 32 + lane], tile[(o4 * 32 + lane) * 49 + s], a);
            acc[di] = a;
        }
    }
#pragma unroll
    for (int di = 0; di < 13; di++) {
        if (di >= nd) break;
        float a = acc[di];
#pragma unroll
        for (int off = 16; off; off >>= 1) a += __shfl_xor_sync(0xffffffffu, a, off);
        if (lane == 0) {
            int d = w + di * 8;
            int cls = d / 49, s = d - cls * 49;
            out_w[CAM_OFF + (n * 2 + cls) * 1568 + b * 49 + s] = fmaxf(a, 0.f);
        }
    }
}

// ---------------------------------------------------------------------------
// Launch
// ---------------------------------------------------------------------------
extern "C" void kernel_launch(void* const* d_in, const int* in_sizes, int n_in,
                              void* d_out, int out_size) {
    const float* x    = (const float*)d_in[0];
    const float* Wb   = (const float*)d_in[1];
    const float* bb   = (const float*)d_in[2];
    const float* p1w  = (const float*)d_in[3];
    const float* p1b  = (const float*)d_in[4];
    const float* p2w  = (const float*)d_in[5];
    const float* p2b  = (const float*)d_in[6];
    const float* clsw = (const float*)d_in[7];
    float* out = (float*)d_out;

    conv_a_kernel<<<(MDIM * KDIM / 2 + 255) / 256, 256>>>(Wb);
    im2col_kernel<<<(NDIM * KDIM / 2 + 255) / 256, 256>>>(x);
    noop_kernel<<<1, 32>>>();   // spacer: puts the GEMM at ncu's capture slot (#4)

    cudaFuncSetAttribute(gemm_mma_kernel, cudaFuncAttributeMaxDynamicSharedMemorySize, SMEM_DYN);
    dim3 ggrid(NPAD / BN, MDIM / BM);   // (13, 48)
    gemm_mma_kernel<<<ggrid, 128, SMEM_DYN>>>(bb, out);

    gap_kernel<<<dim3(NBR * BATCH, 4), 256>>>(out);
    mlp1_kernel<<<dim3(64, NBR), 256>>>(p1w, p1b);
    mlp2_kernel<<<NBR, 256>>>(p2w, p2b, out);
    cam_kernel<<<NBR * BATCH, 256>>>(out, clsw, out);
}

// round 9
// speedup vs baseline: 1.0050x; 1.0050x over previous
#include <cuda_runtime.h>
#include <cuda_fp16.h>
#include <math.h>
#include <stdint.h>

// ---------------------------------------------------------------------------
// RankingCNN: conv(s32,k32) == GEMM C[3072,1568] = Wb[3072,3072] @ P[3072,1568]
// fp32 via fp16 split on legacy tensor cores (mma.sync.m16n8k16):
//   C = Ah*Bh (fp32 acc) + [Ah*Bl + Al*Bh] (fp16 acc, merged at end)
// R9: hoist ALL fragments of a k-chunk (both ks) before issuing 96 HMMAs
// back-to-back -> removes LDSM->HMMA stalls that held tensor pipe at 57%.
// Prep kernels fused into one launch.
// ---------------------------------------------------------------------------

#define NBR 3
#define BATCH 32
#define KDIM 3072
#define MDIM 3072
#define NDIM 1568
#define NPAD 1664            // 13 * 128; pad rows stay zero (static init)
#define RANK_OFF 0
#define CAM_OFF 96
#define FEAT_OFF 9504
#define FPB 1605632
#define FPI 50176

#define BM 64
#define BN 128
#define BK 32
#define NC (KDIM / BK)       // 96 k-chunks

// rows are 64B (32 fp16); swizzle: 16B-chunk index ^= (row>>1)&3
#define A_T 4096             // one A tile (64 x 64B)
#define B_T 8192             // one B tile (128 x 64B)
#define STAGE_B 24576        // Ah | Al | Bh | Bl
#define NSTAGE 4
#define SMEM_DYN (NSTAGE * STAGE_B)   // 98304

// ---- static scratch (no allocations allowed) ------------------------------
__device__ __align__(256) __half g_Ah[MDIM * KDIM];
__device__ __align__(256) __half g_Al[MDIM * KDIM];
__device__ __align__(256) __half g_Bh[NPAD * KDIM];   // pad rows never written -> 0
__device__ __align__(256) __half g_Bl[NPAD * KDIM];
__device__ float g_pooled[NBR * BATCH * 1024];
__device__ float g_h[NBR * BATCH * 512];

// ---- PTX helpers ----------------------------------------------------------
__device__ __forceinline__ uint32_t smem_u32(const void* p) {
    uint32_t a;
    asm("{ .reg .u64 t; cvta.to.shared.u64 t, %1; cvt.u32.u64 %0, t; }" : "=r"(a) : "l"(p));
    return a;
}
__device__ __forceinline__ void cp16(uint32_t dst, const void* src) {
    asm volatile("cp.async.cg.shared.global [%0], [%1], 16;" :: "r"(dst), "l"(src));
}
__device__ __forceinline__ void ldmx4(uint32_t* r, uint32_t a) {
    asm volatile("ldmatrix.sync.aligned.m8n8.x4.shared.b16 {%0,%1,%2,%3}, [%4];"
        : "=r"(r[0]), "=r"(r[1]), "=r"(r[2]), "=r"(r[3]) : "r"(a));
}
__device__ __forceinline__ void mma16816(float* c, const uint32_t* a, const uint32_t* b) {
    asm volatile("mma.sync.aligned.m16n8k16.row.col.f32.f16.f16.f32 "
        "{%0,%1,%2,%3}, {%4,%5,%6,%7}, {%8,%9}, {%0,%1,%2,%3};"
        : "+f"(c[0]), "+f"(c[1]), "+f"(c[2]), "+f"(c[3])
        : "r"(a[0]), "r"(a[1]), "r"(a[2]), "r"(a[3]), "r"(b[0]), "r"(b[1]));
}
__device__ __forceinline__ void mma16816h(uint32_t* c, const uint32_t* a, const uint32_t* b) {
    asm volatile("mma.sync.aligned.m16n8k16.row.col.f16.f16.f16.f16 "
        "{%0,%1}, {%2,%3,%4,%5}, {%6,%7}, {%0,%1};"
        : "+r"(c[0]), "+r"(c[1])
        : "r"(a[0]), "r"(a[1]), "r"(a[2]), "r"(a[3]), "r"(b[0]), "r"(b[1]));
}

// ---------------------------------------------------------------------------
// Kernel 0: no-op spacer (keeps the GEMM at ncu's capture slot)
// ---------------------------------------------------------------------------
__global__ void noop_kernel() {}

// ---------------------------------------------------------------------------
// Kernel 1: fused prep. Blocks [0, A_BLKS) split Wb; rest do im2col + split.
// ---------------------------------------------------------------------------
#define A_BLKS 18432         // (3072*3072/2) / 256
#define B_BLKS 9408          // (1568*3072/2) / 256

__global__ __launch_bounds__(256) void prep_kernel(const float* __restrict__ Wb,
                                                   const float* __restrict__ x) {
    if (blockIdx.x < A_BLKS) {
        int i2 = (blockIdx.x * 256 + threadIdx.x) * 2;
        float2 v = *(const float2*)(Wb + i2);
        __half h0 = __float2half(v.x), h1 = __float2half(v.y);
        __half l0 = __float2half(v.x - __half2float(h0));
        __half l1 = __float2half(v.y - __half2float(h1));
        *(__half2*)(g_Ah + i2) = __half2(h0, h1);
        *(__half2*)(g_Al + i2) = __half2(l0, l1);
    } else {
        int i2 = ((blockIdx.x - A_BLKS) * 256 + threadIdx.x) * 2;
        int n = i2 / KDIM;
        int k = i2 - n * KDIM;          // even
        int c = k >> 10, r = k & 1023, kh = r >> 5, kw = r & 31;
        int b = n / 49, t = n - b * 49, ii = t / 7, jj = t - ii * 7;
        const float* src = x + ((size_t)(b * 3 + c) * 224 + ii * 32 + kh) * 224 + jj * 32 + kw;
        float2 v = *(const float2*)src;
        __half h0 = __float2half(v.x), h1 = __float2half(v.y);
        __half l0 = __float2half(v.x - __half2float(h0));
        __half l1 = __float2half(v.y - __half2float(h1));
        *(__half2*)(g_Bh + i2) = __half2(h0, h1);
        *(__half2*)(g_Bl + i2) = __half2(l0, l1);
    }
}

// ---------------------------------------------------------------------------
// Kernel 3: GEMM 64x128x32 per CTA, 4 warps of 64x32 (1m x 4n), 4 stages.
// All fragments of a chunk loaded before the HMMA block.
// ---------------------------------------------------------------------------
__global__ __launch_bounds__(128, 2) void gemm_mma_kernel(const float* __restrict__ bias,
                                                          float* __restrict__ out) {
    extern __shared__ char smem[];
    const uint32_t s0 = smem_u32(smem);

    const int tid = threadIdx.x;
    const int wid = tid >> 5;          // 0..3  (n quarter)
    const int lane = tid & 31;
    const int mBase = blockIdx.y * BM;
    const int nBase = blockIdx.x * BN;

    // ---- cp.async mapping: 128 thr; thread -> row r = tid>>2, chunk = tid&3
    const int c = tid & 3;
    const int r = tid >> 2;                     // 0..31
    const uint32_t cSw = (uint32_t)((c ^ ((r >> 1) & 3)) << 4);  // same for r+32k
    const uint32_t rOff = (uint32_t)(r * 64) + cSw;
    const __half* gAh = g_Ah + (size_t)(mBase + r) * KDIM + c * 8;
    const __half* gAl = g_Al + (size_t)(mBase + r) * KDIM + c * 8;
    const __half* gBh = g_Bh + (size_t)(nBase + r) * KDIM + c * 8;
    const __half* gBl = g_Bl + (size_t)(nBase + r) * KDIM + c * 8;
    const size_t j32 = (size_t)32 * KDIM;

#define ISSUE(kt) do {                                                          \
        const uint32_t st = s0 + (uint32_t)(((kt) & 3) * STAGE_B);              \
        const int k0 = (kt) * BK;                                               \
        cp16(st + rOff,                 gAh + k0);                              \
        cp16(st + rOff + 2048,          gAh + j32 + k0);                        \
        cp16(st + A_T + rOff,           gAl + k0);                              \
        cp16(st + A_T + rOff + 2048,    gAl + j32 + k0);                        \
        cp16(st + 2*A_T + rOff,         gBh + k0);                              \
        cp16(st + 2*A_T + rOff + 2048,  gBh + j32 + k0);                        \
        cp16(st + 2*A_T + rOff + 4096,  gBh + 2*j32 + k0);                      \
        cp16(st + 2*A_T + rOff + 6144,  gBh + 3*j32 + k0);                      \
        cp16(st + 2*A_T + B_T + rOff,        gBl + k0);                         \
        cp16(st + 2*A_T + B_T + rOff + 2048, gBl + j32 + k0);                   \
        cp16(st + 2*A_T + B_T + rOff + 4096, gBl + 2*j32 + k0);                 \
        cp16(st + 2*A_T + B_T + rOff + 6144, gBl + 3*j32 + k0);                 \
        asm volatile("cp.async.commit_group;");                                 \
    } while (0)

    // ---- accumulators (warp tile 64x32: mf 0..3, nf 0..3) ------------------
    float acc[4][4][4];
    uint32_t acch[4][4][2];
#pragma unroll
    for (int i = 0; i < 4; i++)
#pragma unroll
        for (int j = 0; j < 4; j++) {
#pragma unroll
            for (int q = 0; q < 4; q++) acc[i][j][q] = 0.f;
            acch[i][j][0] = 0u; acch[i][j][1] = 0u;
        }

    // ---- ldmatrix addressing ----------------------------------------------
    const int aR = lane & 15;          // A x4 row within 16
    const int aHi = lane >> 4;
    const int bR = wid * 32 + ((lane >> 4) << 3) + (lane & 7);   // B x4 pair row
    const int bHi = (lane >> 3) & 1;

    ISSUE(0); ISSUE(1); ISSUE(2);

    for (int kt = 0; kt < NC; kt++) {
        asm volatile("cp.async.wait_group 2;");
        __syncthreads();
        if (kt + 3 < NC) ISSUE(kt + 3);
        else asm volatile("cp.async.commit_group;");

        const uint32_t sb = s0 + (uint32_t)((kt & 3) * STAGE_B);

        // ---- load ALL fragments for both ks-steps -------------------------
        uint32_t ah[2][4][4], al[2][4][4], bh[2][4][2], bl[2][4][2];
#pragma unroll
        for (int ks = 0; ks < 2; ks++) {
#pragma unroll
            for (int mf = 0; mf < 4; mf++) {
                const int row = aR + mf * 16;
                const uint32_t ad = sb + (uint32_t)(row * 64)
                    + (uint32_t)(((ks * 2 + aHi) ^ ((row >> 1) & 3)) << 4);
                ldmx4(ah[ks][mf], ad);
                ldmx4(al[ks][mf], ad + A_T);
            }
#pragma unroll
            for (int p = 0; p < 2; p++) {
                const int row = bR + p * 16;
                const uint32_t bd = sb + 2 * A_T + (uint32_t)(row * 64)
                    + (uint32_t)(((ks * 2 + bHi) ^ ((row >> 1) & 3)) << 4);
                uint32_t t[4];
                ldmx4(t, bd);
                bh[ks][2*p][0] = t[0]; bh[ks][2*p][1] = t[1];
                bh[ks][2*p+1][0] = t[2]; bh[ks][2*p+1][1] = t[3];
                ldmx4(t, bd + B_T);
                bl[ks][2*p][0] = t[0]; bl[ks][2*p][1] = t[1];
                bl[ks][2*p+1][0] = t[2]; bl[ks][2*p+1][1] = t[3];
            }
        }

        // ---- 96 HMMAs, no interleaved shared loads ------------------------
#pragma unroll
        for (int ks = 0; ks < 2; ks++)
#pragma unroll
            for (int mf = 0; mf < 4; mf++)
#pragma unroll
                for (int nf = 0; nf < 4; nf++) {
                    mma16816(acc[mf][nf], ah[ks][mf], bh[ks][nf]);
                    mma16816h(acch[mf][nf], ah[ks][mf], bl[ks][nf]);
                    mma16816h(acch[mf][nf], al[ks][mf], bh[ks][nf]);
                }
    }

    // ---- merge fp16 accumulators, bias, scatter to feature layout ----------
#pragma unroll
    for (int mf = 0; mf < 4; mf++) {
        const int m0 = mBase + mf * 16 + (lane >> 2);
        const int m1 = m0 + 8;
        const float bv0 = bias[m0], bv1 = bias[m1];
        float* ob0 = out + FEAT_OFF + (size_t)(m0 >> 10) * FPB + (size_t)(m0 & 1023) * 49;
        float* ob1 = out + FEAT_OFF + (size_t)(m1 >> 10) * FPB + (size_t)(m1 & 1023) * 49;
#pragma unroll
        for (int nf = 0; nf < 4; nf++) {
            const int n = nBase + wid * 32 + nf * 8 + (lane & 3) * 2;
            __half2 lo01 = *(__half2*)&acch[mf][nf][0];
            __half2 lo23 = *(__half2*)&acch[mf][nf][1];
            float v0 = acc[mf][nf][0] + __low2float(lo01);
            float v1 = acc[mf][nf][1] + __high2float(lo01);
            float v2 = acc[mf][nf][2] + __low2float(lo23);
            float v3 = acc[mf][nf][3] + __high2float(lo23);
            if (n < NDIM) {
                int b0 = n / 49,       sA = n - b0 * 49;
                int b1 = (n + 1) / 49, sB = (n + 1) - b1 * 49;
                ob0[(size_t)b0 * FPI + sA] = v0 + bv0;
                ob0[(size_t)b1 * FPI + sB] = v1 + bv0;
                ob1[(size_t)b0 * FPI + sA] = v2 + bv1;
                ob1[(size_t)b1 * FPI + sB] = v3 + bv1;
            }
        }
    }
#undef ISSUE
}

// ---------------------------------------------------------------------------
// Kernel 4: global average pool -> g_pooled[n][b][1024]  (grid 96 x 4)
// ---------------------------------------------------------------------------
__global__ __launch_bounds__(256) void gap_kernel(const float* __restrict__ out) {
    const int n = blockIdx.x >> 5, b = blockIdx.x & 31;
    const int ch = blockIdx.y * 256 + threadIdx.x;
    const float* fo = out + FEAT_OFF + (size_t)n * FPB + (size_t)b * FPI + (size_t)ch * 49;
    float s = 0.f;
#pragma unroll
    for (int q = 0; q < 49; q++) s += fo[q];
    g_pooled[(n * 32 + b) * 1024 + ch] = s * (1.0f / 49.0f);
}

// ---------------------------------------------------------------------------
// Kernel 5: Linear(1024,512)+ReLU, weight-streamed
// ---------------------------------------------------------------------------
__global__ __launch_bounds__(256) void mlp1_kernel(const float* __restrict__ p1w,
                                                   const float* __restrict__ p1b) {
    const int branch = blockIdx.y;
    const int wid = threadIdx.x >> 5, lane = threadIdx.x & 31;
    const int j = blockIdx.x * 8 + wid;
    const float* w = p1w + (size_t)(branch * 512 + j) * 1024;
    float wr[32];
#pragma unroll
    for (int t = 0; t < 32; t++) wr[t] = w[t * 32 + lane];
    const float bj = p1b[branch * 512 + j];
    for (int b = 0; b < 32; b++) {
        const float* pp = g_pooled + (branch * 32 + b) * 1024;
        float s = 0.f;
#pragma unroll
        for (int t = 0; t < 32; t++) s = fmaf(wr[t], pp[t * 32 + lane], s);
#pragma unroll
        for (int off = 16; off; off >>= 1) s += __shfl_xor_sync(0xffffffffu, s, off);
        if (lane == 0) g_h[(branch * 32 + b) * 512 + j] = fmaxf(s + bj, 0.f);
    }
}

// ---------------------------------------------------------------------------
// Kernel 6: Linear(512,2) + softmax[:,1] -> ranking
// ---------------------------------------------------------------------------
__global__ __launch_bounds__(256) void mlp2_kernel(const float* __restrict__ p2w,
                                                   const float* __restrict__ p2b,
                                                   float* __restrict__ out) {
    const int branch = blockIdx.x;
    const int wid = threadIdx.x >> 5, lane = threadIdx.x & 31;
    const float* w0 = p2w + branch * 1024;
    const float* w1 = w0 + 512;
    for (int b = wid; b < 32; b += 8) {
        const float* h = g_h + (branch * 32 + b) * 512;
        float s0 = 0.f, s1 = 0.f;
        for (int t = lane; t < 512; t += 32) {
            float hv = h[t];
            s0 = fmaf(hv, w0[t], s0);
            s1 = fmaf(hv, w1[t], s1);
        }
#pragma unroll
        for (int off = 16; off; off >>= 1) {
            s0 += __shfl_xor_sync(0xffffffffu, s0, off);
            s1 += __shfl_xor_sync(0xffffffffu, s1, off);
        }
        if (lane == 0) {
            float l0 = s0 + p2b[branch * 2 + 0];
            float l1 = s1 + p2b[branch * 2 + 1];
            float mx = fmaxf(l0, l1);
            float e0 = expf(l0 - mx), e1 = expf(l1 - mx);
            out[RANK_OFF + b * 3 + branch] = e1 / (e0 + e1);
        }
    }
}

// ---------------------------------------------------------------------------
// Kernel 7: CAM — 98 dot-products of length 1024 per (branch,image)
// ---------------------------------------------------------------------------
__global__ __launch_bounds__(256) void cam_kernel(const float* __restrict__ out_r,
                                                  const float* __restrict__ clsw,
                                                  float* __restrict__ out_w) {
    __shared__ float wts[2048];
    __shared__ float tile[128 * 49];
    const int n = blockIdx.x >> 5, b = blockIdx.x & 31;
    const int tid = threadIdx.x, w = tid >> 5, lane = tid & 31;
    const float* f = out_r + FEAT_OFF + (size_t)n * FPB + (size_t)b * FPI;

    for (int i = tid; i < 2048; i += 256) wts[i] = clsw[n * 2048 + i];

    const int nd = (w < 2) ? 13 : 12;
    float acc[13];
#pragma unroll
    for (int i = 0; i < 13; i++) acc[i] = 0.f;

    for (int ch = 0; ch < 8; ch++) {
        __syncthreads();
        for (int i = tid; i < 128 * 49; i += 256) tile[i] = f[ch * (128 * 49) + i];
        __syncthreads();
#pragma unroll
        for (int di = 0; di < 13; di++) {
            if (di >= nd) break;
            int d = w + di * 8;
            int cls = d / 49, s = d - cls * 49;
            const float* wp = wts + cls * 1024 + ch * 128;
            float a = acc[di];
#pragma unroll
            for (int o4 = 0; o4 < 4; o4++)
                a = fmaf(wp[o4 * 32 + lane], tile[(o4 * 32 + lane) * 49 + s], a);
            acc[di] = a;
        }
    }
#pragma unroll
    for (int di = 0; di < 13; di++) {
        if (di >= nd) break;
        float a = acc[di];
#pragma unroll
        for (int off = 16; off; off >>= 1) a += __shfl_xor_sync(0xffffffffu, a, off);
        if (lane == 0) {
            int d = w + di * 8;
            int cls = d / 49, s = d - cls * 49;
            out_w[CAM_OFF + (n * 2 + cls) * 1568 + b * 49 + s] = fmaxf(a, 0.f);
        }
    }
}

// ---------------------------------------------------------------------------
// Launch
// ---------------------------------------------------------------------------
extern "C" void kernel_launch(void* const* d_in, const int* in_sizes, int n_in,
                              void* d_out, int out_size) {
    const float* x    = (const float*)d_in[0];
    const float* Wb   = (const float*)d_in[1];
    const float* bb   = (const float*)d_in[2];
    const float* p1w  = (const float*)d_in[3];
    const float* p1b  = (const float*)d_in[4];
    const float* p2w  = (const float*)d_in[5];
    const float* p2b  = (const float*)d_in[6];
    const float* clsw = (const float*)d_in[7];
    float* out = (float*)d_out;

    prep_kernel<<<A_BLKS + B_BLKS, 256>>>(Wb, x);
    noop_kernel<<<1, 32>>>();
    noop_kernel<<<1, 32>>>();   // spacers: keep GEMM at ncu's capture slot

    cudaFuncSetAttribute(gemm_mma_kernel, cudaFuncAttributeMaxDynamicSharedMemorySize, SMEM_DYN);
    dim3 ggrid(NPAD / BN, MDIM / BM);   // (13, 48)
    gemm_mma_kernel<<<ggrid, 128, SMEM_DYN>>>(bb, out);

    gap_kernel<<<dim3(NBR * BATCH, 4), 256>>>(out);
    mlp1_kernel<<<dim3(64, NBR), 256>>>(p1w, p1b);
    mlp2_kernel<<<NBR, 256>>>(p2w, p2b, out);
    cam_kernel<<<NBR * BATCH, 256>>>(out, clsw, out);
}

// round 10
// speedup vs baseline: 1.2862x; 1.2798x over previous
#include <cuda_runtime.h>
#include <cuda_fp16.h>
#include <math.h>
#include <stdint.h>

// ---------------------------------------------------------------------------
// RankingCNN: conv(s32,k32) == GEMM C[3072,1568] = Wb[3072,3072] @ P[3072,1568]
// R10: 2-term fp16 emulation — C = Ah*Bh (f32 acc) + Al*Bh (f16 acc) = A*fp16(B).
// Legacy mma.sync runs at rt~16/SMSP regardless of acc type (measured R8/R9),
// so instruction COUNT is the wall: 3 terms -> 2 terms = -33% GEMM time.
// B-split dropped everywhere (prep, smem, cp.async). GAP fused into CAM.
// ---------------------------------------------------------------------------

#define NBR 3
#define BATCH 32
#define KDIM 3072
#define MDIM 3072
#define NDIM 1568
#define NPAD 1664            // 13 * 128; pad rows stay zero (static init)
#define RANK_OFF 0
#define CAM_OFF 96
#define FEAT_OFF 9504
#define FPB 1605632
#define FPI 50176

#define BM 64
#define BN 128
#define BK 32
#define NC (KDIM / BK)       // 96 k-chunks

// rows are 64B (32 fp16); swizzle: 16B-chunk index ^= (row>>1)&3
#define A_T 4096             // one A tile (64 x 64B)
#define B_T 8192             // one B tile (128 x 64B)
#define STAGE_B 16384        // Ah | Al | Bh
#define NSTAGE 4
#define SMEM_DYN (NSTAGE * STAGE_B)   // 65536

// ---- static scratch (no allocations allowed) ------------------------------
__device__ __align__(256) __half g_Ah[MDIM * KDIM];
__device__ __align__(256) __half g_Al[MDIM * KDIM];
__device__ __align__(256) __half g_Bh[NPAD * KDIM];   // pad rows never written -> 0
__device__ float g_pooled[NBR * BATCH * 1024];
__device__ float g_h[NBR * BATCH * 512];

// ---- PTX helpers ----------------------------------------------------------
__device__ __forceinline__ uint32_t smem_u32(const void* p) {
    uint32_t a;
    asm("{ .reg .u64 t; cvta.to.shared.u64 t, %1; cvt.u32.u64 %0, t; }" : "=r"(a) : "l"(p));
    return a;
}
__device__ __forceinline__ void cp16(uint32_t dst, const void* src) {
    asm volatile("cp.async.cg.shared.global [%0], [%1], 16;" :: "r"(dst), "l"(src));
}
__device__ __forceinline__ void ldmx4(uint32_t* r, uint32_t a) {
    asm volatile("ldmatrix.sync.aligned.m8n8.x4.shared.b16 {%0,%1,%2,%3}, [%4];"
        : "=r"(r[0]), "=r"(r[1]), "=r"(r[2]), "=r"(r[3]) : "r"(a));
}
__device__ __forceinline__ void mma16816(float* c, const uint32_t* a, const uint32_t* b) {
    asm volatile("mma.sync.aligned.m16n8k16.row.col.f32.f16.f16.f32 "
        "{%0,%1,%2,%3}, {%4,%5,%6,%7}, {%8,%9}, {%0,%1,%2,%3};"
        : "+f"(c[0]), "+f"(c[1]), "+f"(c[2]), "+f"(c[3])
        : "r"(a[0]), "r"(a[1]), "r"(a[2]), "r"(a[3]), "r"(b[0]), "r"(b[1]));
}
__device__ __forceinline__ void mma16816h(uint32_t* c, const uint32_t* a, const uint32_t* b) {
    asm volatile("mma.sync.aligned.m16n8k16.row.col.f16.f16.f16.f16 "
        "{%0,%1}, {%2,%3,%4,%5}, {%6,%7}, {%0,%1};"
        : "+r"(c[0]), "+r"(c[1])
        : "r"(a[0]), "r"(a[1]), "r"(a[2]), "r"(a[3]), "r"(b[0]), "r"(b[1]));
}

// ---------------------------------------------------------------------------
// Kernel 0: no-op spacer (keeps the GEMM at ncu's capture slot)
// ---------------------------------------------------------------------------
__global__ void noop_kernel() {}

// ---------------------------------------------------------------------------
// Kernel 1: fused prep. Blocks [0, A_BLKS) split Wb; rest im2col B -> fp16.
// ---------------------------------------------------------------------------
#define A_BLKS 18432         // (3072*3072/2) / 256
#define B_BLKS 9408          // (1568*3072/2) / 256

__global__ __launch_bounds__(256) void prep_kernel(const float* __restrict__ Wb,
                                                   const float* __restrict__ x) {
    if (blockIdx.x < A_BLKS) {
        int i2 = (blockIdx.x * 256 + threadIdx.x) * 2;
        float2 v = *(const float2*)(Wb + i2);
        __half h0 = __float2half(v.x), h1 = __float2half(v.y);
        __half l0 = __float2half(v.x - __half2float(h0));
        __half l1 = __float2half(v.y - __half2float(h1));
        *(__half2*)(g_Ah + i2) = __half2(h0, h1);
        *(__half2*)(g_Al + i2) = __half2(l0, l1);
    } else {
        int i2 = ((blockIdx.x - A_BLKS) * 256 + threadIdx.x) * 2;
        int n = i2 / KDIM;
        int k = i2 - n * KDIM;          // even
        int c = k >> 10, r = k & 1023, kh = r >> 5, kw = r & 31;
        int b = n / 49, t = n - b * 49, ii = t / 7, jj = t - ii * 7;
        const float* src = x + ((size_t)(b * 3 + c) * 224 + ii * 32 + kh) * 224 + jj * 32 + kw;
        float2 v = *(const float2*)src;
        *(__half2*)(g_Bh + i2) = __half2(__float2half(v.x), __float2half(v.y));
    }
}

// ---------------------------------------------------------------------------
// Kernel 3: GEMM 64x128x32 per CTA, 4 warps of 64x32 (1m x 4n), 4 stages.
// 2 terms: Ah*Bh (f32 acc), Al*Bh (f16 acc).
// ---------------------------------------------------------------------------
__global__ __launch_bounds__(128, 2) void gemm_mma_kernel(const float* __restrict__ bias,
                                                          float* __restrict__ out) {
    extern __shared__ char smem[];
    const uint32_t s0 = smem_u32(smem);

    const int tid = threadIdx.x;
    const int wid = tid >> 5;          // 0..3  (n quarter)
    const int lane = tid & 31;
    const int mBase = blockIdx.y * BM;
    const int nBase = blockIdx.x * BN;

    // ---- cp.async mapping: 128 thr; thread -> row r = tid>>2, chunk = tid&3
    const int c = tid & 3;
    const int r = tid >> 2;                     // 0..31
    const uint32_t cSw = (uint32_t)((c ^ ((r >> 1) & 3)) << 4);  // same for r+32k
    const uint32_t rOff = (uint32_t)(r * 64) + cSw;
    const __half* gAh = g_Ah + (size_t)(mBase + r) * KDIM + c * 8;
    const __half* gAl = g_Al + (size_t)(mBase + r) * KDIM + c * 8;
    const __half* gBh = g_Bh + (size_t)(nBase + r) * KDIM + c * 8;
    const size_t j32 = (size_t)32 * KDIM;

#define ISSUE(kt) do {                                                          \
        const uint32_t st = s0 + (uint32_t)(((kt) & 3) * STAGE_B);              \
        const int k0 = (kt) * BK;                                               \
        cp16(st + rOff,                 gAh + k0);                              \
        cp16(st + rOff + 2048,          gAh + j32 + k0);                        \
        cp16(st + A_T + rOff,           gAl + k0);                              \
        cp16(st + A_T + rOff + 2048,    gAl + j32 + k0);                        \
        cp16(st + 2*A_T + rOff,         gBh + k0);                              \
        cp16(st + 2*A_T + rOff + 2048,  gBh + j32 + k0);                        \
        cp16(st + 2*A_T + rOff + 4096,  gBh + 2*j32 + k0);                      \
        cp16(st + 2*A_T + rOff + 6144,  gBh + 3*j32 + k0);                      \
        asm volatile("cp.async.commit_group;");                                 \
    } while (0)

    // ---- accumulators (warp tile 64x32: mf 0..3, nf 0..3) ------------------
    float acc[4][4][4];
    uint32_t acch[4][4][2];
#pragma unroll
    for (int i = 0; i < 4; i++)
#pragma unroll
        for (int j = 0; j < 4; j++) {
#pragma unroll
            for (int q = 0; q < 4; q++) acc[i][j][q] = 0.f;
            acch[i][j][0] = 0u; acch[i][j][1] = 0u;
        }

    // ---- ldmatrix addressing ----------------------------------------------
    const int aR = lane & 15;          // A x4 row within 16
    const int aHi = lane >> 4;
    const int bR = wid * 32 + ((lane >> 4) << 3) + (lane & 7);   // B x4 pair row
    const int bHi = (lane >> 3) & 1;

    ISSUE(0); ISSUE(1); ISSUE(2);

    for (int kt = 0; kt < NC; kt++) {
        asm volatile("cp.async.wait_group 2;");
        __syncthreads();
        if (kt + 3 < NC) ISSUE(kt + 3);
        else asm volatile("cp.async.commit_group;");

        const uint32_t sb = s0 + (uint32_t)((kt & 3) * STAGE_B);

        uint32_t ah[2][4][4], al[2][4][4], bh[2][4][2];
#pragma unroll
        for (int ks = 0; ks < 2; ks++) {
#pragma unroll
            for (int mf = 0; mf < 4; mf++) {
                const int row = aR + mf * 16;
                const uint32_t ad = sb + (uint32_t)(row * 64)
                    + (uint32_t)(((ks * 2 + aHi) ^ ((row >> 1) & 3)) << 4);
                ldmx4(ah[ks][mf], ad);
                ldmx4(al[ks][mf], ad + A_T);
            }
#pragma unroll
            for (int p = 0; p < 2; p++) {
                const int row = bR + p * 16;
                const uint32_t bd = sb + 2 * A_T + (uint32_t)(row * 64)
                    + (uint32_t)(((ks * 2 + bHi) ^ ((row >> 1) & 3)) << 4);
                uint32_t t[4];
                ldmx4(t, bd);
                bh[ks][2*p][0] = t[0]; bh[ks][2*p][1] = t[1];
                bh[ks][2*p+1][0] = t[2]; bh[ks][2*p+1][1] = t[3];
            }
        }

        // ---- 64 HMMAs ------------------------------------------------------
#pragma unroll
        for (int ks = 0; ks < 2; ks++)
#pragma unroll
            for (int mf = 0; mf < 4; mf++)
#pragma unroll
                for (int nf = 0; nf < 4; nf++) {
                    mma16816(acc[mf][nf], ah[ks][mf], bh[ks][nf]);
                    mma16816h(acch[mf][nf], al[ks][mf], bh[ks][nf]);
                }
    }

    // ---- merge fp16 accumulators, bias, scatter to feature layout ----------
#pragma unroll
    for (int mf = 0; mf < 4; mf++) {
        const int m0 = mBase + mf * 16 + (lane >> 2);
        const int m1 = m0 + 8;
        const float bv0 = bias[m0], bv1 = bias[m1];
        float* ob0 = out + FEAT_OFF + (size_t)(m0 >> 10) * FPB + (size_t)(m0 & 1023) * 49;
        float* ob1 = out + FEAT_OFF + (size_t)(m1 >> 10) * FPB + (size_t)(m1 & 1023) * 49;
#pragma unroll
        for (int nf = 0; nf < 4; nf++) {
            const int n = nBase + wid * 32 + nf * 8 + (lane & 3) * 2;
            __half2 lo01 = *(__half2*)&acch[mf][nf][0];
            __half2 lo23 = *(__half2*)&acch[mf][nf][1];
            float v0 = acc[mf][nf][0] + __low2float(lo01);
            float v1 = acc[mf][nf][1] + __high2float(lo01);
            float v2 = acc[mf][nf][2] + __low2float(lo23);
            float v3 = acc[mf][nf][3] + __high2float(lo23);
            if (n < NDIM) {
                int b0 = n / 49,       sA = n - b0 * 49;
                int b1 = (n + 1) / 49, sB = (n + 1) - b1 * 49;
                ob0[(size_t)b0 * FPI + sA] = v0 + bv0;
                ob0[(size_t)b1 * FPI + sB] = v1 + bv0;
                ob1[(size_t)b0 * FPI + sA] = v2 + bv1;
                ob1[(size_t)b1 * FPI + sB] = v3 + bv1;
            }
        }
    }
#undef ISSUE
}

// ---------------------------------------------------------------------------
// Kernel 4: fused GAP + CAM — single pass over features per (branch,image)
// ---------------------------------------------------------------------------
__global__ __launch_bounds__(256) void postproc_kernel(const float* __restrict__ out_r,
                                                       const float* __restrict__ clsw,
                                                       float* __restrict__ out_w) {
    __shared__ float wts[2048];
    __shared__ float tile[128 * 49];
    const int n = blockIdx.x >> 5, b = blockIdx.x & 31;
    const int tid = threadIdx.x, w = tid >> 5, lane = tid & 31;
    const float* f = out_r + FEAT_OFF + (size_t)n * FPB + (size_t)b * FPI;
    float* pooled = g_pooled + (n * 32 + b) * 1024;

    for (int i = tid; i < 2048; i += 256) wts[i] = clsw[n * 2048 + i];

    const int nd = (w < 2) ? 13 : 12;
    float acc[13];
#pragma unroll
    for (int i = 0; i < 13; i++) acc[i] = 0.f;

    for (int ch = 0; ch < 8; ch++) {
        __syncthreads();
        for (int i = tid; i < 128 * 49; i += 256) tile[i] = f[ch * (128 * 49) + i];
        __syncthreads();
        // GAP: threads 0..127 each own one channel of this chunk (stride-49
        // smem reads, 49 odd -> conflict-free)
        if (tid < 128) {
            float s = 0.f;
            const float* tp = tile + tid * 49;
#pragma unroll
            for (int q = 0; q < 49; q++) s += tp[q];
            pooled[ch * 128 + tid] = s * (1.0f / 49.0f);
        }
        // CAM partial dots
#pragma unroll
        for (int di = 0; di < 13; di++) {
            if (di >= nd) break;
            int d = w + di * 8;
            int cls = d / 49, s = d - cls * 49;
            const float* wp = wts + cls * 1024 + ch * 128;
            float a = acc[di];
#pragma unroll
            for (int o4 = 0; o4 < 4; o4++)
                a = fmaf(wp[o4 * 32 + lane], tile[(o4 * 32 + lane) * 49 + s], a);
            acc[di] = a;
        }
    }
#pragma unroll
    for (int di = 0; di < 13; di++) {
        if (di >= nd) break;
        float a = acc[di];
#pragma unroll
        for (int off = 16; off; off >>= 1) a += __shfl_xor_sync(0xffffffffu, a, off);
        if (lane == 0) {
            int d = w + di * 8;
            int cls = d / 49, s = d - cls * 49;
            out_w[CAM_OFF + (n * 2 + cls) * 1568 + b * 49 + s] = fmaxf(a, 0.f);
        }
    }
}

// ---------------------------------------------------------------------------
// Kernel 5: Linear(1024,512)+ReLU, weight-streamed
// ---------------------------------------------------------------------------
__global__ __launch_bounds__(256) void mlp1_kernel(const float* __restrict__ p1w,
                                                   const float* __restrict__ p1b) {
    const int branch = blockIdx.y;
    const int wid = threadIdx.x >> 5, lane = threadIdx.x & 31;
    const int j = blockIdx.x * 8 + wid;
    const float* w = p1w + (size_t)(branch * 512 + j) * 1024;
    float wr[32];
#pragma unroll
    for (int t = 0; t < 32; t++) wr[t] = w[t * 32 + lane];
    const float bj = p1b[branch * 512 + j];
    for (int b = 0; b < 32; b++) {
        const float* pp = g_pooled + (branch * 32 + b) * 1024;
        float s = 0.f;
#pragma unroll
        for (int t = 0; t < 32; t++) s = fmaf(wr[t], pp[t * 32 + lane], s);
#pragma unroll
        for (int off = 16; off; off >>= 1) s += __shfl_xor_sync(0xffffffffu, s, off);
        if (lane == 0) g_h[(branch * 32 + b) * 512 + j] = fmaxf(s + bj, 0.f);
    }
}

// ---------------------------------------------------------------------------
// Kernel 6: Linear(512,2) + softmax[:,1] -> ranking
// ---------------------------------------------------------------------------
__global__ __launch_bounds__(256) void mlp2_kernel(const float* __restrict__ p2w,
                                                   const float* __restrict__ p2b,
                                                   float* __restrict__ out) {
    const int branch = blockIdx.x;
    const int wid = threadIdx.x >> 5, lane = threadIdx.x & 31;
    const float* w0 = p2w + branch * 1024;
    const float* w1 = w0 + 512;
    for (int b = wid; b < 32; b += 8) {
        const float* h = g_h + (branch * 32 + b) * 512;
        float s0 = 0.f, s1 = 0.f;
        for (int t = lane; t < 512; t += 32) {
            float hv = h[t];
            s0 = fmaf(hv, w0[t], s0);
            s1 = fmaf(hv, w1[t], s1);
        }
#pragma unroll
        for (int off = 16; off; off >>= 1) {
            s0 += __shfl_xor_sync(0xffffffffu, s0, off);
            s1 += __shfl_xor_sync(0xffffffffu, s1, off);
        }
        if (lane == 0) {
            float l0 = s0 + p2b[branch * 2 + 0];
            float l1 = s1 + p2b[branch * 2 + 1];
            float mx = fmaxf(l0, l1);
            float e0 = expf(l0 - mx), e1 = expf(l1 - mx);
            out[RANK_OFF + b * 3 + branch] = e1 / (e0 + e1);
        }
    }
}

// ---------------------------------------------------------------------------
// Launch
// ---------------------------------------------------------------------------
extern "C" void kernel_launch(void* const* d_in, const int* in_sizes, int n_in,
                              void* d_out, int out_size) {
    const float* x    = (const float*)d_in[0];
    const float* Wb   = (const float*)d_in[1];
    const float* bb   = (const float*)d_in[2];
    const float* p1w  = (const float*)d_in[3];
    const float* p1b  = (const float*)d_in[4];
    const float* p2w  = (const float*)d_in[5];
    const float* p2b  = (const float*)d_in[6];
    const float* clsw = (const float*)d_in[7];
    float* out = (float*)d_out;

    prep_kernel<<<A_BLKS + B_BLKS, 256>>>(Wb, x);
    noop_kernel<<<1, 32>>>();
    noop_kernel<<<1, 32>>>();   // spacers: keep GEMM at ncu's capture slot

    cudaFuncSetAttribute(gemm_mma_kernel, cudaFuncAttributeMaxDynamicSharedMemorySize, SMEM_DYN);
    dim3 ggrid(NPAD / BN, MDIM / BM);   // (13, 48)
    gemm_mma_kernel<<<ggrid, 128, SMEM_DYN>>>(bb, out);

    postproc_kernel<<<NBR * BATCH, 256>>>(out, clsw, out);
    mlp1_kernel<<<dim3(64, NBR), 256>>>(p1w, p1b);
    mlp2_kernel<<<NBR, 256>>>(p2w, p2b, out);
}

// round 11
// speedup vs baseline: 1.8107x; 1.4079x over previous
#include <cuda_runtime.h>
#include <cuda_fp16.h>
#include <math.h>
#include <stdint.h>

// ---------------------------------------------------------------------------
// RankingCNN: conv(s32,k32) == GEMM C[3072,1568] = Wb[3072,3072] @ P[3072,1568]
// R11: single-term pure-fp16 GEMM (C = fp16(A)*fp16(B), fp32 accumulate).
// Measured rt~16cyc/HMMA uniform (R8-R10) -> time == HMMA count. Calibrated
// error: B-only quant = 2.08e-4 -> A+B ~ 2.9e-4 < 1e-3 threshold.
// 3 CTAs/SM (48KB smem/CTA), 4-stage cp.async.
// ---------------------------------------------------------------------------

#define NBR 3
#define BATCH 32
#define KDIM 3072
#define MDIM 3072
#define NDIM 1568
#define NPAD 1664            // 13 * 128; pad rows stay zero (static init)
#define RANK_OFF 0
#define CAM_OFF 96
#define FEAT_OFF 9504
#define FPB 1605632
#define FPI 50176

#define BM 64
#define BN 128
#define BK 32
#define NC (KDIM / BK)       // 96 k-chunks

// rows are 64B (32 fp16); swizzle: 16B-chunk index ^= (row>>1)&3
#define A_T 4096             // A tile (64 x 64B)
#define B_T 8192             // B tile (128 x 64B)
#define STAGE_B 12288        // Ah | Bh
#define NSTAGE 4
#define SMEM_DYN (NSTAGE * STAGE_B)   // 49152

// ---- static scratch (no allocations allowed) ------------------------------
__device__ __align__(256) __half g_Ah[MDIM * KDIM];
__device__ __align__(256) __half g_Bh[NPAD * KDIM];   // pad rows never written -> 0
__device__ float g_pooled[NBR * BATCH * 1024];
__device__ float g_h[NBR * BATCH * 512];

// ---- PTX helpers ----------------------------------------------------------
__device__ __forceinline__ uint32_t smem_u32(const void* p) {
    uint32_t a;
    asm("{ .reg .u64 t; cvta.to.shared.u64 t, %1; cvt.u32.u64 %0, t; }" : "=r"(a) : "l"(p));
    return a;
}
__device__ __forceinline__ void cp16(uint32_t dst, const void* src) {
    asm volatile("cp.async.cg.shared.global [%0], [%1], 16;" :: "r"(dst), "l"(src));
}
__device__ __forceinline__ void ldmx4(uint32_t* r, uint32_t a) {
    asm volatile("ldmatrix.sync.aligned.m8n8.x4.shared.b16 {%0,%1,%2,%3}, [%4];"
        : "=r"(r[0]), "=r"(r[1]), "=r"(r[2]), "=r"(r[3]) : "r"(a));
}
__device__ __forceinline__ void mma16816(float* c, const uint32_t* a, const uint32_t* b) {
    asm volatile("mma.sync.aligned.m16n8k16.row.col.f32.f16.f16.f32 "
        "{%0,%1,%2,%3}, {%4,%5,%6,%7}, {%8,%9}, {%0,%1,%2,%3};"
        : "+f"(c[0]), "+f"(c[1]), "+f"(c[2]), "+f"(c[3])
        : "r"(a[0]), "r"(a[1]), "r"(a[2]), "r"(a[3]), "r"(b[0]), "r"(b[1]));
}

// ---------------------------------------------------------------------------
// Kernel 0: no-op spacer (keeps the GEMM at ncu's capture slot)
// ---------------------------------------------------------------------------
__global__ void noop_kernel() {}

// ---------------------------------------------------------------------------
// Kernel 1: fused prep. Blocks [0, A_BLKS): Wb -> fp16; rest: im2col -> fp16.
// ---------------------------------------------------------------------------
#define A_BLKS 18432         // (3072*3072/2) / 256
#define B_BLKS 9408          // (1568*3072/2) / 256

__global__ __launch_bounds__(256) void prep_kernel(const float* __restrict__ Wb,
                                                   const float* __restrict__ x) {
    if (blockIdx.x < A_BLKS) {
        int i2 = (blockIdx.x * 256 + threadIdx.x) * 2;
        float2 v = *(const float2*)(Wb + i2);
        *(__half2*)(g_Ah + i2) = __half2(__float2half(v.x), __float2half(v.y));
    } else {
        int i2 = ((blockIdx.x - A_BLKS) * 256 + threadIdx.x) * 2;
        int n = i2 / KDIM;
        int k = i2 - n * KDIM;          // even
        int c = k >> 10, r = k & 1023, kh = r >> 5, kw = r & 31;
        int b = n / 49, t = n - b * 49, ii = t / 7, jj = t - ii * 7;
        const float* src = x + ((size_t)(b * 3 + c) * 224 + ii * 32 + kh) * 224 + jj * 32 + kw;
        float2 v = *(const float2*)src;
        *(__half2*)(g_Bh + i2) = __half2(__float2half(v.x), __float2half(v.y));
    }
}

// ---------------------------------------------------------------------------
// Kernel 3: GEMM 64x128x32 per CTA, 4 warps of 64x32 (1m x 4n), 4 stages.
// Single term: fp16 x fp16 -> fp32.
// ---------------------------------------------------------------------------
__global__ __launch_bounds__(128, 3) void gemm_mma_kernel(const float* __restrict__ bias,
                                                          float* __restrict__ out) {
    extern __shared__ char smem[];
    const uint32_t s0 = smem_u32(smem);

    const int tid = threadIdx.x;
    const int wid = tid >> 5;          // 0..3  (n quarter)
    const int lane = tid & 31;
    const int mBase = blockIdx.y * BM;
    const int nBase = blockIdx.x * BN;

    // ---- cp.async mapping: 128 thr; thread -> row r = tid>>2, chunk = tid&3
    const int c = tid & 3;
    const int r = tid >> 2;                     // 0..31
    const uint32_t cSw = (uint32_t)((c ^ ((r >> 1) & 3)) << 4);  // same for r+32k
    const uint32_t rOff = (uint32_t)(r * 64) + cSw;
    const __half* gAh = g_Ah + (size_t)(mBase + r) * KDIM + c * 8;
    const __half* gBh = g_Bh + (size_t)(nBase + r) * KDIM + c * 8;
    const size_t j32 = (size_t)32 * KDIM;

#define ISSUE(kt) do {                                                          \
        const uint32_t st = s0 + (uint32_t)(((kt) & 3) * STAGE_B);              \
        const int k0 = (kt) * BK;                                               \
        cp16(st + rOff,               gAh + k0);                                \
        cp16(st + rOff + 2048,        gAh + j32 + k0);                          \
        cp16(st + A_T + rOff,         gBh + k0);                                \
        cp16(st + A_T + rOff + 2048,  gBh + j32 + k0);                          \
        cp16(st + A_T + rOff + 4096,  gBh + 2*j32 + k0);                        \
        cp16(st + A_T + rOff + 6144,  gBh + 3*j32 + k0);                        \
        asm volatile("cp.async.commit_group;");                                 \
    } while (0)

    // ---- accumulators (warp tile 64x32: mf 0..3, nf 0..3) ------------------
    float acc[4][4][4];
#pragma unroll
    for (int i = 0; i < 4; i++)
#pragma unroll
        for (int j = 0; j < 4; j++)
#pragma unroll
            for (int q = 0; q < 4; q++) acc[i][j][q] = 0.f;

    // ---- ldmatrix addressing ----------------------------------------------
    const int aR = lane & 15;          // A x4 row within 16
    const int aHi = lane >> 4;
    const int bR = wid * 32 + ((lane >> 4) << 3) + (lane & 7);   // B x4 pair row
    const int bHi = (lane >> 3) & 1;

    ISSUE(0); ISSUE(1); ISSUE(2);

    for (int kt = 0; kt < NC; kt++) {
        asm volatile("cp.async.wait_group 2;");
        __syncthreads();
        if (kt + 3 < NC) ISSUE(kt + 3);
        else asm volatile("cp.async.commit_group;");

        const uint32_t sb = s0 + (uint32_t)((kt & 3) * STAGE_B);

        uint32_t ah[2][4][4], bh[2][4][2];
#pragma unroll
        for (int ks = 0; ks < 2; ks++) {
#pragma unroll
            for (int mf = 0; mf < 4; mf++) {
                const int row = aR + mf * 16;
                const uint32_t ad = sb + (uint32_t)(row * 64)
                    + (uint32_t)(((ks * 2 + aHi) ^ ((row >> 1) & 3)) << 4);
                ldmx4(ah[ks][mf], ad);
            }
#pragma unroll
            for (int p = 0; p < 2; p++) {
                const int row = bR + p * 16;
                const uint32_t bd = sb + A_T + (uint32_t)(row * 64)
                    + (uint32_t)(((ks * 2 + bHi) ^ ((row >> 1) & 3)) << 4);
                uint32_t t[4];
                ldmx4(t, bd);
                bh[ks][2*p][0] = t[0]; bh[ks][2*p][1] = t[1];
                bh[ks][2*p+1][0] = t[2]; bh[ks][2*p+1][1] = t[3];
            }
        }

        // ---- 32 HMMAs ------------------------------------------------------
#pragma unroll
        for (int ks = 0; ks < 2; ks++)
#pragma unroll
            for (int mf = 0; mf < 4; mf++)
#pragma unroll
                for (int nf = 0; nf < 4; nf++)
                    mma16816(acc[mf][nf], ah[ks][mf], bh[ks][nf]);
    }

    // ---- bias + scatter to feature layout ----------------------------------
#pragma unroll
    for (int mf = 0; mf < 4; mf++) {
        const int m0 = mBase + mf * 16 + (lane >> 2);
        const int m1 = m0 + 8;
        const float bv0 = bias[m0], bv1 = bias[m1];
        float* ob0 = out + FEAT_OFF + (size_t)(m0 >> 10) * FPB + (size_t)(m0 & 1023) * 49;
        float* ob1 = out + FEAT_OFF + (size_t)(m1 >> 10) * FPB + (size_t)(m1 & 1023) * 49;
#pragma unroll
        for (int nf = 0; nf < 4; nf++) {
            const int n = nBase + wid * 32 + nf * 8 + (lane & 3) * 2;
            if (n < NDIM) {
                int b0 = n / 49,       sA = n - b0 * 49;
                int b1 = (n + 1) / 49, sB = (n + 1) - b1 * 49;
                ob0[(size_t)b0 * FPI + sA] = acc[mf][nf][0] + bv0;
                ob0[(size_t)b1 * FPI + sB] = acc[mf][nf][1] + bv0;
                ob1[(size_t)b0 * FPI + sA] = acc[mf][nf][2] + bv1;
                ob1[(size_t)b1 * FPI + sB] = acc[mf][nf][3] + bv1;
            }
        }
    }
#undef ISSUE
}

// ---------------------------------------------------------------------------
// Kernel 4: fused GAP + CAM — single pass over features per (branch,image)
// ---------------------------------------------------------------------------
__global__ __launch_bounds__(256) void postproc_kernel(const float* __restrict__ out_r,
                                                       const float* __restrict__ clsw,
                                                       float* __restrict__ out_w) {
    __shared__ float wts[2048];
    __shared__ float tile[128 * 49];
    const int n = blockIdx.x >> 5, b = blockIdx.x & 31;
    const int tid = threadIdx.x, w = tid >> 5, lane = tid & 31;
    const float* f = out_r + FEAT_OFF + (size_t)n * FPB + (size_t)b * FPI;
    float* pooled = g_pooled + (n * 32 + b) * 1024;

    for (int i = tid; i < 2048; i += 256) wts[i] = clsw[n * 2048 + i];

    const int nd = (w < 2) ? 13 : 12;
    float acc[13];
#pragma unroll
    for (int i = 0; i < 13; i++) acc[i] = 0.f;

    for (int ch = 0; ch < 8; ch++) {
        __syncthreads();
        for (int i = tid; i < 128 * 49; i += 256) tile[i] = f[ch * (128 * 49) + i];
        __syncthreads();
        // GAP: threads 0..127 own one channel each (stride-49, conflict-free)
        if (tid < 128) {
            float s = 0.f;
            const float* tp = tile + tid * 49;
#pragma unroll
            for (int q = 0; q < 49; q++) s += tp[q];
            pooled[ch * 128 + tid] = s * (1.0f / 49.0f);
        }
        // CAM partial dots
#pragma unroll
        for (int di = 0; di < 13; di++) {
            if (di >= nd) break;
            int d = w + di * 8;
            int cls = d / 49, s = d - cls * 49;
            const float* wp = wts + cls * 1024 + ch * 128;
            float a = acc[di];
#pragma unroll
            for (int o4 = 0; o4 < 4; o4++)
                a = fmaf(wp[o4 * 32 + lane], tile[(o4 * 32 + lane) * 49 + s], a);
            acc[di] = a;
        }
    }
#pragma unroll
    for (int di = 0; di < 13; di++) {
        if (di >= nd) break;
        float a = acc[di];
#pragma unroll
        for (int off = 16; off; off >>= 1) a += __shfl_xor_sync(0xffffffffu, a, off);
        if (lane == 0) {
            int d = w + di * 8;
            int cls = d / 49, s = d - cls * 49;
            out_w[CAM_OFF + (n * 2 + cls) * 1568 + b * 49 + s] = fmaxf(a, 0.f);
        }
    }
}

// ---------------------------------------------------------------------------
// Kernel 5: Linear(1024,512)+ReLU, weight-streamed
// ---------------------------------------------------------------------------
__global__ __launch_bounds__(256) void mlp1_kernel(const float* __restrict__ p1w,
                                                   const float* __restrict__ p1b) {
    const int branch = blockIdx.y;
    const int wid = threadIdx.x >> 5, lane = threadIdx.x & 31;
    const int j = blockIdx.x * 8 + wid;
    const float* w = p1w + (size_t)(branch * 512 + j) * 1024;
    float wr[32];
#pragma unroll
    for (int t = 0; t < 32; t++) wr[t] = w[t * 32 + lane];
    const float bj = p1b[branch * 512 + j];
    for (int b = 0; b < 32; b++) {
        const float* pp = g_pooled + (branch * 32 + b) * 1024;
        float s = 0.f;
#pragma unroll
        for (int t = 0; t < 32; t++) s = fmaf(wr[t], pp[t * 32 + lane], s);
#pragma unroll
        for (int off = 16; off; off >>= 1) s += __shfl_xor_sync(0xffffffffu, s, off);
        if (lane == 0) g_h[(branch * 32 + b) * 512 + j] = fmaxf(s + bj, 0.f);
    }
}

// ---------------------------------------------------------------------------
// Kernel 6: Linear(512,2) + softmax[:,1] -> ranking
// ---------------------------------------------------------------------------
__global__ __launch_bounds__(256) void mlp2_kernel(const float* __restrict__ p2w,
                                                   const float* __restrict__ p2b,
                                                   float* __restrict__ out) {
    const int branch = blockIdx.x;
    const int wid = threadIdx.x >> 5, lane = threadIdx.x & 31;
    const float* w0 = p2w + branch * 1024;
    const float* w1 = w0 + 512;
    for (int b = wid; b < 32; b += 8) {
        const float* h = g_h + (branch * 32 + b) * 512;
        float s0 = 0.f, s1 = 0.f;
        for (int t = lane; t < 512; t += 32) {
            float hv = h[t];
            s0 = fmaf(hv, w0[t], s0);
            s1 = fmaf(hv, w1[t], s1);
        }
#pragma unroll
        for (int off = 16; off; off >>= 1) {
            s0 += __shfl_xor_sync(0xffffffffu, s0, off);
            s1 += __shfl_xor_sync(0xffffffffu, s1, off);
        }
        if (lane == 0) {
            float l0 = s0 + p2b[branch * 2 + 0];
            float l1 = s1 + p2b[branch * 2 + 1];
            float mx = fmaxf(l0, l1);
            float e0 = expf(l0 - mx), e1 = expf(l1 - mx);
            out[RANK_OFF + b * 3 + branch] = e1 / (e0 + e1);
        }
    }
}

// ---------------------------------------------------------------------------
// Launch
// ---------------------------------------------------------------------------
extern "C" void kernel_launch(void* const* d_in, const int* in_sizes, int n_in,
                              void* d_out, int out_size) {
    const float* x    = (const float*)d_in[0];
    const float* Wb   = (const float*)d_in[1];
    const float* bb   = (const float*)d_in[2];
    const float* p1w  = (const float*)d_in[3];
    const float* p1b  = (const float*)d_in[4];
    const float* p2w  = (const float*)d_in[5];
    const float* p2b  = (const float*)d_in[6];
    const float* clsw = (const float*)d_in[7];
    float* out = (float*)d_out;

    prep_kernel<<<A_BLKS + B_BLKS, 256>>>(Wb, x);
    noop_kernel<<<1, 32>>>();
    noop_kernel<<<1, 32>>>();   // spacers: keep GEMM at ncu's capture slot

    cudaFuncSetAttribute(gemm_mma_kernel, cudaFuncAttributeMaxDynamicSharedMemorySize, SMEM_DYN);
    dim3 ggrid(NPAD / BN, MDIM / BM);   // (13, 48)
    gemm_mma_kernel<<<ggrid, 128, SMEM_DYN>>>(bb, out);

    postproc_kernel<<<NBR * BATCH, 256>>>(out, clsw, out);
    mlp1_kernel<<<dim3(64, NBR), 256>>>(p1w, p1b);
    mlp2_kernel<<<NBR, 256>>>(p2w, p2b, out);
}

// round 12
// speedup vs baseline: 2.0593x; 1.1373x over previous
#include <cuda_runtime.h>
#include <cuda_fp16.h>
#include <math.h>
#include <stdint.h>

// ---------------------------------------------------------------------------
// RankingCNN: conv(s32,k32) == GEMM C[3072,1568] = Wb[3072,3072] @ P[3072,1568]
// R12: GEMM at its HMMA-dispatch floor (115us). Non-GEMM rework:
//  - postproc split per channel-chunk (768 blocks), partial CAM -> g_camp
//  - CAM finalize fused into mlp1
//  - launch order puts postproc at ncu capture slot
// ---------------------------------------------------------------------------

#define NBR 3
#define BATCH 32
#define KDIM 3072
#define MDIM 3072
#define NDIM 1568
#define NPAD 1664            // 13 * 128; pad rows stay zero (static init)
#define RANK_OFF 0
#define CAM_OFF 96
#define FEAT_OFF 9504
#define FPB 1605632
#define FPI 50176

#define BM 64
#define BN 128
#define BK 32
#define NC (KDIM / BK)       // 96 k-chunks

#define A_T 4096             // A tile (64 x 64B)
#define STAGE_B 12288        // Ah | Bh
#define NSTAGE 4
#define SMEM_DYN (NSTAGE * STAGE_B)   // 49152

// ---- static scratch (no allocations allowed) ------------------------------
__device__ __align__(256) __half g_Ah[MDIM * KDIM];
__device__ __align__(256) __half g_Bh[NPAD * KDIM];   // pad rows never written -> 0
__device__ float g_pooled[NBR * BATCH * 1024];
__device__ float g_h[NBR * BATCH * 512];
__device__ float g_camp[8 * NBR * 2 * NDIM];          // per-chunk CAM partials

// ---- PTX helpers ----------------------------------------------------------
__device__ __forceinline__ uint32_t smem_u32(const void* p) {
    uint32_t a;
    asm("{ .reg .u64 t; cvta.to.shared.u64 t, %1; cvt.u32.u64 %0, t; }" : "=r"(a) : "l"(p));
    return a;
}
__device__ __forceinline__ void cp16(uint32_t dst, const void* src) {
    asm volatile("cp.async.cg.shared.global [%0], [%1], 16;" :: "r"(dst), "l"(src));
}
__device__ __forceinline__ void ldmx4(uint32_t* r, uint32_t a) {
    asm volatile("ldmatrix.sync.aligned.m8n8.x4.shared.b16 {%0,%1,%2,%3}, [%4];"
        : "=r"(r[0]), "=r"(r[1]), "=r"(r[2]), "=r"(r[3]) : "r"(a));
}
__device__ __forceinline__ void mma16816(float* c, const uint32_t* a, const uint32_t* b) {
    asm volatile("mma.sync.aligned.m16n8k16.row.col.f32.f16.f16.f32 "
        "{%0,%1,%2,%3}, {%4,%5,%6,%7}, {%8,%9}, {%0,%1,%2,%3};"
        : "+f"(c[0]), "+f"(c[1]), "+f"(c[2]), "+f"(c[3])
        : "r"(a[0]), "r"(a[1]), "r"(a[2]), "r"(a[3]), "r"(b[0]), "r"(b[1]));
}

__global__ void noop_kernel() {}

// ---------------------------------------------------------------------------
// Kernel 1: fused prep. Blocks [0, A_BLKS): Wb -> fp16; rest: im2col -> fp16.
// ---------------------------------------------------------------------------
#define A_BLKS 18432         // (3072*3072/2) / 256
#define B_BLKS 9408          // (1568*3072/2) / 256

__global__ __launch_bounds__(256) void prep_kernel(const float* __restrict__ Wb,
                                                   const float* __restrict__ x) {
    if (blockIdx.x < A_BLKS) {
        int i2 = (blockIdx.x * 256 + threadIdx.x) * 2;
        float2 v = *(const float2*)(Wb + i2);
        *(__half2*)(g_Ah + i2) = __half2(__float2half(v.x), __float2half(v.y));
    } else {
        int i2 = ((blockIdx.x - A_BLKS) * 256 + threadIdx.x) * 2;
        int n = i2 / KDIM;
        int k = i2 - n * KDIM;          // even
        int c = k >> 10, r = k & 1023, kh = r >> 5, kw = r & 31;
        int b = n / 49, t = n - b * 49, ii = t / 7, jj = t - ii * 7;
        const float* src = x + ((size_t)(b * 3 + c) * 224 + ii * 32 + kh) * 224 + jj * 32 + kw;
        float2 v = *(const float2*)src;
        *(__half2*)(g_Bh + i2) = __half2(__float2half(v.x), __float2half(v.y));
    }
}

// ---------------------------------------------------------------------------
// Kernel 2: GEMM 64x128x32 per CTA, 4 warps of 64x32 (1m x 4n), 4 stages.
// ---------------------------------------------------------------------------
__global__ __launch_bounds__(128, 3) void gemm_mma_kernel(const float* __restrict__ bias,
                                                          float* __restrict__ out) {
    extern __shared__ char smem[];
    const uint32_t s0 = smem_u32(smem);

    const int tid = threadIdx.x;
    const int wid = tid >> 5;
    const int lane = tid & 31;
    const int mBase = blockIdx.y * BM;
    const int nBase = blockIdx.x * BN;

    const int c = tid & 3;
    const int r = tid >> 2;                     // 0..31
    const uint32_t cSw = (uint32_t)((c ^ ((r >> 1) & 3)) << 4);
    const uint32_t rOff = (uint32_t)(r * 64) + cSw;
    const __half* gAh = g_Ah + (size_t)(mBase + r) * KDIM + c * 8;
    const __half* gBh = g_Bh + (size_t)(nBase + r) * KDIM + c * 8;
    const size_t j32 = (size_t)32 * KDIM;

#define ISSUE(kt) do {                                                          \
        const uint32_t st = s0 + (uint32_t)(((kt) & 3) * STAGE_B);              \
        const int k0 = (kt) * BK;                                               \
        cp16(st + rOff,               gAh + k0);                                \
        cp16(st + rOff + 2048,        gAh + j32 + k0);                          \
        cp16(st + A_T + rOff,         gBh + k0);                                \
        cp16(st + A_T + rOff + 2048,  gBh + j32 + k0);                          \
        cp16(st + A_T + rOff + 4096,  gBh + 2*j32 + k0);                        \
        cp16(st + A_T + rOff + 6144,  gBh + 3*j32 + k0);                        \
        asm volatile("cp.async.commit_group;");                                 \
    } while (0)

    float acc[4][4][4];
#pragma unroll
    for (int i = 0; i < 4; i++)
#pragma unroll
        for (int j = 0; j < 4; j++)
#pragma unroll
            for (int q = 0; q < 4; q++) acc[i][j][q] = 0.f;

    const int aR = lane & 15;
    const int aHi = lane >> 4;
    const int bR = wid * 32 + ((lane >> 4) << 3) + (lane & 7);
    const int bHi = (lane >> 3) & 1;

    ISSUE(0); ISSUE(1); ISSUE(2);

    for (int kt = 0; kt < NC; kt++) {
        asm volatile("cp.async.wait_group 2;");
        __syncthreads();
        if (kt + 3 < NC) ISSUE(kt + 3);
        else asm volatile("cp.async.commit_group;");

        const uint32_t sb = s0 + (uint32_t)((kt & 3) * STAGE_B);

        uint32_t ah[2][4][4], bh[2][4][2];
#pragma unroll
        for (int ks = 0; ks < 2; ks++) {
#pragma unroll
            for (int mf = 0; mf < 4; mf++) {
                const int row = aR + mf * 16;
                const uint32_t ad = sb + (uint32_t)(row * 64)
                    + (uint32_t)(((ks * 2 + aHi) ^ ((row >> 1) & 3)) << 4);
                ldmx4(ah[ks][mf], ad);
            }
#pragma unroll
            for (int p = 0; p < 2; p++) {
                const int row = bR + p * 16;
                const uint32_t bd = sb + A_T + (uint32_t)(row * 64)
                    + (uint32_t)(((ks * 2 + bHi) ^ ((row >> 1) & 3)) << 4);
                uint32_t t[4];
                ldmx4(t, bd);
                bh[ks][2*p][0] = t[0]; bh[ks][2*p][1] = t[1];
                bh[ks][2*p+1][0] = t[2]; bh[ks][2*p+1][1] = t[3];
            }
        }

#pragma unroll
        for (int ks = 0; ks < 2; ks++)
#pragma unroll
            for (int mf = 0; mf < 4; mf++)
#pragma unroll
                for (int nf = 0; nf < 4; nf++)
                    mma16816(acc[mf][nf], ah[ks][mf], bh[ks][nf]);
    }

#pragma unroll
    for (int mf = 0; mf < 4; mf++) {
        const int m0 = mBase + mf * 16 + (lane >> 2);
        const int m1 = m0 + 8;
        const float bv0 = bias[m0], bv1 = bias[m1];
        float* ob0 = out + FEAT_OFF + (size_t)(m0 >> 10) * FPB + (size_t)(m0 & 1023) * 49;
        float* ob1 = out + FEAT_OFF + (size_t)(m1 >> 10) * FPB + (size_t)(m1 & 1023) * 49;
#pragma unroll
        for (int nf = 0; nf < 4; nf++) {
            const int n = nBase + wid * 32 + nf * 8 + (lane & 3) * 2;
            if (n < NDIM) {
                int b0 = n / 49,       sA = n - b0 * 49;
                int b1 = (n + 1) / 49, sB = (n + 1) - b1 * 49;
                ob0[(size_t)b0 * FPI + sA] = acc[mf][nf][0] + bv0;
                ob0[(size_t)b1 * FPI + sB] = acc[mf][nf][1] + bv0;
                ob1[(size_t)b0 * FPI + sA] = acc[mf][nf][2] + bv1;
                ob1[(size_t)b1 * FPI + sB] = acc[mf][nf][3] + bv1;
            }
        }
    }
#undef ISSUE
}

// ---------------------------------------------------------------------------
// Kernel 3: postproc — grid (96, 8): one block per (branch,image,chunk).
// Per 128-channel chunk: GAP slice (disjoint) + partial CAM -> g_camp.
// ---------------------------------------------------------------------------
__global__ __launch_bounds__(256) void postproc_kernel(const float* __restrict__ out_r,
                                                       const float* __restrict__ clsw) {
    __shared__ float tile[128 * 49];
    __shared__ float wsh[256];
    const int n = blockIdx.x >> 5, b = blockIdx.x & 31;
    const int ch = blockIdx.y;
    const int tid = threadIdx.x, w = tid >> 5, lane = tid & 31;
    const float* f = out_r + FEAT_OFF + (size_t)n * FPB + (size_t)b * FPI + ch * (128 * 49);

    // weights slice: [2][128] for this chunk
    if (tid < 256) {
        int cls = tid >> 7, j = tid & 127;
        wsh[tid] = clsw[n * 2048 + cls * 1024 + ch * 128 + j];
    }
    // tile load, vectorized (6272 floats = 1568 float4)
    {
        const float4* f4 = (const float4*)f;
        float4* t4 = (float4*)tile;
        for (int i = tid; i < 1568; i += 256) t4[i] = f4[i];
    }
    __syncthreads();

    // GAP slice: threads 0..127 each own one channel (stride-49, conflict-free)
    if (tid < 128) {
        float s = 0.f;
        const float* tp = tile + tid * 49;
#pragma unroll
        for (int q = 0; q < 49; q++) s += tp[q];
        g_pooled[(n * 32 + b) * 1024 + ch * 128 + tid] = s * (1.0f / 49.0f);
    }

    // partial CAM: 98 dots of length 128
    const int nd = (w < 2) ? 13 : 12;
#pragma unroll
    for (int di = 0; di < 13; di++) {
        if (di >= nd) break;
        int d = w + di * 8;
        int cls = d / 49, s = d - cls * 49;
        const float* wp = wsh + cls * 128;
        float a = 0.f;
#pragma unroll
        for (int o4 = 0; o4 < 4; o4++)
            a = fmaf(wp[o4 * 32 + lane], tile[(o4 * 32 + lane) * 49 + s], a);
#pragma unroll
        for (int off = 16; off; off >>= 1) a += __shfl_xor_sync(0xffffffffu, a, off);
        if (lane == 0)
            g_camp[ch * (NBR * 2 * NDIM) + (n * 2 + cls) * NDIM + b * 49 + s] = a;
    }
}

// ---------------------------------------------------------------------------
// Kernel 4: mlp1 (Linear 1024->512 + ReLU) + fused CAM finalize
// grid (64, NBR)
// ---------------------------------------------------------------------------
__global__ __launch_bounds__(256) void mlp1_kernel(const float* __restrict__ p1w,
                                                   const float* __restrict__ p1b,
                                                   float* __restrict__ out) {
    const int branch = blockIdx.y;
    const int wid = threadIdx.x >> 5, lane = threadIdx.x & 31;
    const int tid = threadIdx.x;

    // ---- CAM finalize: this block owns 49 outputs --------------------------
    if (tid < 49) {
        int idx = branch * (2 * NDIM) + blockIdx.x * 49 + tid;   // within branch span
        float s = 0.f;
#pragma unroll
        for (int ch = 0; ch < 8; ch++) s += g_camp[ch * (NBR * 2 * NDIM) + idx];
        out[CAM_OFF + idx] = fmaxf(s, 0.f);
    }

    // ---- Linear(1024,512)+ReLU, weight-streamed ----------------------------
    const int j = blockIdx.x * 8 + wid;
    const float* wgt = p1w + (size_t)(branch * 512 + j) * 1024;
    float wr[32];
#pragma unroll
    for (int t = 0; t < 32; t++) wr[t] = wgt[t * 32 + lane];
    const float bj = p1b[branch * 512 + j];
    for (int b = 0; b < 32; b++) {
        const float* pp = g_pooled + (branch * 32 + b) * 1024;
        float s = 0.f;
#pragma unroll
        for (int t = 0; t < 32; t++) s = fmaf(wr[t], pp[t * 32 + lane], s);
#pragma unroll
        for (int off = 16; off; off >>= 1) s += __shfl_xor_sync(0xffffffffu, s, off);
        if (lane == 0) g_h[(branch * 32 + b) * 512 + j] = fmaxf(s + bj, 0.f);
    }
}

// ---------------------------------------------------------------------------
// Kernel 5: Linear(512,2) + softmax[:,1] -> ranking
// ---------------------------------------------------------------------------
__global__ __launch_bounds__(256) void mlp2_kernel(const float* __restrict__ p2w,
                                                   const float* __restrict__ p2b,
                                                   float* __restrict__ out) {
    const int branch = blockIdx.x;
    const int wid = threadIdx.x >> 5, lane = threadIdx.x & 31;
    const float* w0 = p2w + branch * 1024;
    const float* w1 = w0 + 512;
    for (int b = wid; b < 32; b += 8) {
        const float* h = g_h + (branch * 32 + b) * 512;
        float s0 = 0.f, s1 = 0.f;
        for (int t = lane; t < 512; t += 32) {
            float hv = h[t];
            s0 = fmaf(hv, w0[t], s0);
            s1 = fmaf(hv, w1[t], s1);
        }
#pragma unroll
        for (int off = 16; off; off >>= 1) {
            s0 += __shfl_xor_sync(0xffffffffu, s0, off);
            s1 += __shfl_xor_sync(0xffffffffu, s1, off);
        }
        if (lane == 0) {
            float l0 = s0 + p2b[branch * 2 + 0];
            float l1 = s1 + p2b[branch * 2 + 1];
            float mx = fmaxf(l0, l1);
            float e0 = expf(l0 - mx), e1 = expf(l1 - mx);
            out[RANK_OFF + b * 3 + branch] = e1 / (e0 + e1);
        }
    }
}

// ---------------------------------------------------------------------------
// Launch: prep(1), gemm(2), noop(3), postproc(4 <- ncu slot), mlp1(5), mlp2(6)
// ---------------------------------------------------------------------------
extern "C" void kernel_launch(void* const* d_in, const int* in_sizes, int n_in,
                              void* d_out, int out_size) {
    const float* x    = (const float*)d_in[0];
    const float* Wb   = (const float*)d_in[1];
    const float* bb   = (const float*)d_in[2];
    const float* p1w  = (const float*)d_in[3];
    const float* p1b  = (const float*)d_in[4];
    const float* p2w  = (const float*)d_in[5];
    const float* p2b  = (const float*)d_in[6];
    const float* clsw = (const float*)d_in[7];
    float* out = (float*)d_out;

    prep_kernel<<<A_BLKS + B_BLKS, 256>>>(Wb, x);

    cudaFuncSetAttribute(gemm_mma_kernel, cudaFuncAttributeMaxDynamicSharedMemorySize, SMEM_DYN);
    dim3 ggrid(NPAD / BN, MDIM / BM);   // (13, 48)
    gemm_mma_kernel<<<ggrid, 128, SMEM_DYN>>>(bb, out);

    noop_kernel<<<1, 32>>>();           // spacer: postproc -> ncu capture slot

    postproc_kernel<<<dim3(NBR * BATCH, 8), 256>>>(out, clsw);
    mlp1_kernel<<<dim3(64, NBR), 256>>>(p1w, p1b, out);
    mlp2_kernel<<<NBR, 256>>>(p2w, p2b, out);
}

// round 13
// speedup vs baseline: 2.1654x; 1.0515x over previous
#include <cuda_runtime.h>
#include <cuda_fp16.h>
#include <math.h>
#include <stdint.h>

// ---------------------------------------------------------------------------
// RankingCNN: conv(s32,k32) == GEMM C[3072,1568] = Wb[3072,3072] @ P[3072,1568]
// R13: prep vectorized to float4 (4 elems/thread, 16B ld / 8B st) — it was the
// largest non-GEMM cost (~50us inferred). mlp2 widened to 96 blocks. noop
// dropped (ncu slot -> mlp1).
// ---------------------------------------------------------------------------

#define NBR 3
#define BATCH 32
#define KDIM 3072
#define MDIM 3072
#define NDIM 1568
#define NPAD 1664            // 13 * 128; pad rows stay zero (static init)
#define RANK_OFF 0
#define CAM_OFF 96
#define FEAT_OFF 9504
#define FPB 1605632
#define FPI 50176

#define BM 64
#define BN 128
#define BK 32
#define NC (KDIM / BK)       // 96 k-chunks

#define A_T 4096             // A tile (64 x 64B)
#define STAGE_B 12288        // Ah | Bh
#define NSTAGE 4
#define SMEM_DYN (NSTAGE * STAGE_B)   // 49152

// ---- static scratch (no allocations allowed) ------------------------------
__device__ __align__(256) __half g_Ah[MDIM * KDIM];
__device__ __align__(256) __half g_Bh[NPAD * KDIM];   // pad rows never written -> 0
__device__ float g_pooled[NBR * BATCH * 1024];
__device__ float g_h[NBR * BATCH * 512];
__device__ float g_camp[8 * NBR * 2 * NDIM];          // per-chunk CAM partials

// ---- PTX helpers ----------------------------------------------------------
__device__ __forceinline__ uint32_t smem_u32(const void* p) {
    uint32_t a;
    asm("{ .reg .u64 t; cvta.to.shared.u64 t, %1; cvt.u32.u64 %0, t; }" : "=r"(a) : "l"(p));
    return a;
}
__device__ __forceinline__ void cp16(uint32_t dst, const void* src) {
    asm volatile("cp.async.cg.shared.global [%0], [%1], 16;" :: "r"(dst), "l"(src));
}
__device__ __forceinline__ void ldmx4(uint32_t* r, uint32_t a) {
    asm volatile("ldmatrix.sync.aligned.m8n8.x4.shared.b16 {%0,%1,%2,%3}, [%4];"
        : "=r"(r[0]), "=r"(r[1]), "=r"(r[2]), "=r"(r[3]) : "r"(a));
}
__device__ __forceinline__ void mma16816(float* c, const uint32_t* a, const uint32_t* b) {
    asm volatile("mma.sync.aligned.m16n8k16.row.col.f32.f16.f16.f32 "
        "{%0,%1,%2,%3}, {%4,%5,%6,%7}, {%8,%9}, {%0,%1,%2,%3};"
        : "+f"(c[0]), "+f"(c[1]), "+f"(c[2]), "+f"(c[3])
        : "r"(a[0]), "r"(a[1]), "r"(a[2]), "r"(a[3]), "r"(b[0]), "r"(b[1]));
}
__device__ __forceinline__ uint2 cvt4(float4 v) {
    __half2 lo = __floats2half2_rn(v.x, v.y);
    __half2 hi = __floats2half2_rn(v.z, v.w);
    uint2 o;
    o.x = *(uint32_t*)&lo;
    o.y = *(uint32_t*)&hi;
    return o;
}

// ---------------------------------------------------------------------------
// Kernel 1: fused prep, float4 per thread.
// Blocks [0, A4_BLKS): Wb -> fp16. Rest: im2col x -> fp16.
// ---------------------------------------------------------------------------
#define A4_BLKS 9216         // (3072*3072/4) / 256
#define B4_BLKS 4704         // (1568*3072/4) / 256

__global__ __launch_bounds__(256) void prep_kernel(const float* __restrict__ Wb,
                                                   const float* __restrict__ x) {
    if (blockIdx.x < A4_BLKS) {
        int i4 = (blockIdx.x * 256 + threadIdx.x) * 4;
        float4 v = *(const float4*)(Wb + i4);
        *(uint2*)(g_Ah + i4) = cvt4(v);
    } else {
        int i4 = ((blockIdx.x - A4_BLKS) * 256 + threadIdx.x) * 4;
        int n = i4 / KDIM;
        int k = i4 - n * KDIM;          // multiple of 4 -> kw multiple of 4
        int c = k >> 10, r = k & 1023, kh = r >> 5, kw = r & 31;
        int b = n / 49, t = n - b * 49, ii = t / 7, jj = t - ii * 7;
        const float* src = x + ((size_t)(b * 3 + c) * 224 + ii * 32 + kh) * 224 + jj * 32 + kw;
        float4 v = *(const float4*)src;
        *(uint2*)(g_Bh + i4) = cvt4(v);
    }
}

// ---------------------------------------------------------------------------
// Kernel 2: GEMM 64x128x32 per CTA, 4 warps of 64x32 (1m x 4n), 4 stages.
// ---------------------------------------------------------------------------
__global__ __launch_bounds__(128, 3) void gemm_mma_kernel(const float* __restrict__ bias,
                                                          float* __restrict__ out) {
    extern __shared__ char smem[];
    const uint32_t s0 = smem_u32(smem);

    const int tid = threadIdx.x;
    const int wid = tid >> 5;
    const int lane = tid & 31;
    const int mBase = blockIdx.y * BM;
    const int nBase = blockIdx.x * BN;

    const int c = tid & 3;
    const int r = tid >> 2;                     // 0..31
    const uint32_t cSw = (uint32_t)((c ^ ((r >> 1) & 3)) << 4);
    const uint32_t rOff = (uint32_t)(r * 64) + cSw;
    const __half* gAh = g_Ah + (size_t)(mBase + r) * KDIM + c * 8;
    const __half* gBh = g_Bh + (size_t)(nBase + r) * KDIM + c * 8;
    const size_t j32 = (size_t)32 * KDIM;

#define ISSUE(kt) do {                                                          \
        const uint32_t st = s0 + (uint32_t)(((kt) & 3) * STAGE_B);              \
        const int k0 = (kt) * BK;                                               \
        cp16(st + rOff,               gAh + k0);                                \
        cp16(st + rOff + 2048,        gAh + j32 + k0);                          \
        cp16(st + A_T + rOff,         gBh + k0);                                \
        cp16(st + A_T + rOff + 2048,  gBh + j32 + k0);                          \
        cp16(st + A_T + rOff + 4096,  gBh + 2*j32 + k0);                        \
        cp16(st + A_T + rOff + 6144,  gBh + 3*j32 + k0);                        \
        asm volatile("cp.async.commit_group;");                                 \
    } while (0)

    float acc[4][4][4];
#pragma unroll
    for (int i = 0; i < 4; i++)
#pragma unroll
        for (int j = 0; j < 4; j++)
#pragma unroll
            for (int q = 0; q < 4; q++) acc[i][j][q] = 0.f;

    const int aR = lane & 15;
    const int aHi = lane >> 4;
    const int bR = wid * 32 + ((lane >> 4) << 3) + (lane & 7);
    const int bHi = (lane >> 3) & 1;

    ISSUE(0); ISSUE(1); ISSUE(2);

    for (int kt = 0; kt < NC; kt++) {
        asm volatile("cp.async.wait_group 2;");
        __syncthreads();
        if (kt + 3 < NC) ISSUE(kt + 3);
        else asm volatile("cp.async.commit_group;");

        const uint32_t sb = s0 + (uint32_t)((kt & 3) * STAGE_B);

        uint32_t ah[2][4][4], bh[2][4][2];
#pragma unroll
        for (int ks = 0; ks < 2; ks++) {
#pragma unroll
            for (int mf = 0; mf < 4; mf++) {
                const int row = aR + mf * 16;
                const uint32_t ad = sb + (uint32_t)(row * 64)
                    + (uint32_t)(((ks * 2 + aHi) ^ ((row >> 1) & 3)) << 4);
                ldmx4(ah[ks][mf], ad);
            }
#pragma unroll
            for (int p = 0; p < 2; p++) {
                const int row = bR + p * 16;
                const uint32_t bd = sb + A_T + (uint32_t)(row * 64)
                    + (uint32_t)(((ks * 2 + bHi) ^ ((row >> 1) & 3)) << 4);
                uint32_t t[4];
                ldmx4(t, bd);
                bh[ks][2*p][0] = t[0]; bh[ks][2*p][1] = t[1];
                bh[ks][2*p+1][0] = t[2]; bh[ks][2*p+1][1] = t[3];
            }
        }

#pragma unroll
        for (int ks = 0; ks < 2; ks++)
#pragma unroll
            for (int mf = 0; mf < 4; mf++)
#pragma unroll
                for (int nf = 0; nf < 4; nf++)
                    mma16816(acc[mf][nf], ah[ks][mf], bh[ks][nf]);
    }

#pragma unroll
    for (int mf = 0; mf < 4; mf++) {
        const int m0 = mBase + mf * 16 + (lane >> 2);
        const int m1 = m0 + 8;
        const float bv0 = bias[m0], bv1 = bias[m1];
        float* ob0 = out + FEAT_OFF + (size_t)(m0 >> 10) * FPB + (size_t)(m0 & 1023) * 49;
        float* ob1 = out + FEAT_OFF + (size_t)(m1 >> 10) * FPB + (size_t)(m1 & 1023) * 49;
#pragma unroll
        for (int nf = 0; nf < 4; nf++) {
            const int n = nBase + wid * 32 + nf * 8 + (lane & 3) * 2;
            if (n < NDIM) {
                int b0 = n / 49,       sA = n - b0 * 49;
                int b1 = (n + 1) / 49, sB = (n + 1) - b1 * 49;
                ob0[(size_t)b0 * FPI + sA] = acc[mf][nf][0] + bv0;
                ob0[(size_t)b1 * FPI + sB] = acc[mf][nf][1] + bv0;
                ob1[(size_t)b0 * FPI + sA] = acc[mf][nf][2] + bv1;
                ob1[(size_t)b1 * FPI + sB] = acc[mf][nf][3] + bv1;
            }
        }
    }
#undef ISSUE
}

// ---------------------------------------------------------------------------
// Kernel 3: postproc — grid (96, 8): one block per (branch,image,chunk).
// ---------------------------------------------------------------------------
__global__ __launch_bounds__(256) void postproc_kernel(const float* __restrict__ out_r,
                                                       const float* __restrict__ clsw) {
    __shared__ float tile[128 * 49];
    __shared__ float wsh[256];
    const int n = blockIdx.x >> 5, b = blockIdx.x & 31;
    const int ch = blockIdx.y;
    const int tid = threadIdx.x, w = tid >> 5, lane = tid & 31;
    const float* f = out_r + FEAT_OFF + (size_t)n * FPB + (size_t)b * FPI + ch * (128 * 49);

    if (tid < 256) {
        int cls = tid >> 7, j = tid & 127;
        wsh[tid] = clsw[n * 2048 + cls * 1024 + ch * 128 + j];
    }
    {
        const float4* f4 = (const float4*)f;
        float4* t4 = (float4*)tile;
        for (int i = tid; i < 1568; i += 256) t4[i] = f4[i];
    }
    __syncthreads();

    if (tid < 128) {
        float s = 0.f;
        const float* tp = tile + tid * 49;
#pragma unroll
        for (int q = 0; q < 49; q++) s += tp[q];
        g_pooled[(n * 32 + b) * 1024 + ch * 128 + tid] = s * (1.0f / 49.0f);
    }

    const int nd = (w < 2) ? 13 : 12;
#pragma unroll
    for (int di = 0; di < 13; di++) {
        if (di >= nd) break;
        int d = w + di * 8;
        int cls = d / 49, s = d - cls * 49;
        const float* wp = wsh + cls * 128;
        float a = 0.f;
#pragma unroll
        for (int o4 = 0; o4 < 4; o4++)
            a = fmaf(wp[o4 * 32 + lane], tile[(o4 * 32 + lane) * 49 + s], a);
#pragma unroll
        for (int off = 16; off; off >>= 1) a += __shfl_xor_sync(0xffffffffu, a, off);
        if (lane == 0)
            g_camp[ch * (NBR * 2 * NDIM) + (n * 2 + cls) * NDIM + b * 49 + s] = a;
    }
}

// ---------------------------------------------------------------------------
// Kernel 4: mlp1 (Linear 1024->512 + ReLU) + fused CAM finalize
// ---------------------------------------------------------------------------
__global__ __launch_bounds__(256) void mlp1_kernel(const float* __restrict__ p1w,
                                                   const float* __restrict__ p1b,
                                                   float* __restrict__ out) {
    const int branch = blockIdx.y;
    const int wid = threadIdx.x >> 5, lane = threadIdx.x & 31;
    const int tid = threadIdx.x;

    if (tid < 49) {
        int idx = branch * (2 * NDIM) + blockIdx.x * 49 + tid;
        float s = 0.f;
#pragma unroll
        for (int ch = 0; ch < 8; ch++) s += g_camp[ch * (NBR * 2 * NDIM) + idx];
        out[CAM_OFF + idx] = fmaxf(s, 0.f);
    }

    const int j = blockIdx.x * 8 + wid;
    const float* wgt = p1w + (size_t)(branch * 512 + j) * 1024;
    float wr[32];
#pragma unroll
    for (int t = 0; t < 32; t++) wr[t] = wgt[t * 32 + lane];
    const float bj = p1b[branch * 512 + j];
    for (int b = 0; b < 32; b++) {
        const float* pp = g_pooled + (branch * 32 + b) * 1024;
        float s = 0.f;
#pragma unroll
        for (int t = 0; t < 32; t++) s = fmaf(wr[t], pp[t * 32 + lane], s);
#pragma unroll
        for (int off = 16; off; off >>= 1) s += __shfl_xor_sync(0xffffffffu, s, off);
        if (lane == 0) g_h[(branch * 32 + b) * 512 + j] = fmaxf(s + bj, 0.f);
    }
}

// ---------------------------------------------------------------------------
// Kernel 5: Linear(512,2) + softmax[:,1] — grid 96 (one block per branch,image)
// ---------------------------------------------------------------------------
__global__ __launch_bounds__(64) void mlp2_kernel(const float* __restrict__ p2w,
                                                  const float* __restrict__ p2b,
                                                  float* __restrict__ out) {
    const int branch = blockIdx.x / 32, b = blockIdx.x & 31;
    const int wid = threadIdx.x >> 5, lane = threadIdx.x & 31;
    const float* wv = p2w + branch * 1024 + wid * 512;
    const float* h = g_h + (branch * 32 + b) * 512;
    float s = 0.f;
#pragma unroll
    for (int t = 0; t < 16; t++) s = fmaf(h[t * 32 + lane], wv[t * 32 + lane], s);
#pragma unroll
    for (int off = 16; off; off >>= 1) s += __shfl_xor_sync(0xffffffffu, s, off);
    __shared__ float logit[2];
    if (lane == 0) logit[wid] = s + p2b[branch * 2 + wid];
    __syncthreads();
    if (threadIdx.x == 0) {
        float l0 = logit[0], l1 = logit[1];
        float mx = fmaxf(l0, l1);
        float e0 = expf(l0 - mx), e1 = expf(l1 - mx);
        out[RANK_OFF + b * 3 + branch] = e1 / (e0 + e1);
    }
}

// ---------------------------------------------------------------------------
// Launch: prep(1), gemm(2), postproc(3), mlp1(4 <- ncu slot), mlp2(5)
// ---------------------------------------------------------------------------
extern "C" void kernel_launch(void* const* d_in, const int* in_sizes, int n_in,
                              void* d_out, int out_size) {
    const float* x    = (const float*)d_in[0];
    const float* Wb   = (const float*)d_in[1];
    const float* bb   = (const float*)d_in[2];
    const float* p1w  = (const float*)d_in[3];
    const float* p1b  = (const float*)d_in[4];
    const float* p2w  = (const float*)d_in[5];
    const float* p2b  = (const float*)d_in[6];
    const float* clsw = (const float*)d_in[7];
    float* out = (float*)d_out;

    prep_kernel<<<A4_BLKS + B4_BLKS, 256>>>(Wb, x);

    cudaFuncSetAttribute(gemm_mma_kernel, cudaFuncAttributeMaxDynamicSharedMemorySize, SMEM_DYN);
    dim3 ggrid(NPAD / BN, MDIM / BM);   // (13, 48)
    gemm_mma_kernel<<<ggrid, 128, SMEM_DYN>>>(bb, out);

    postproc_kernel<<<dim3(NBR * BATCH, 8), 256>>>(out, clsw);
    mlp1_kernel<<<dim3(64, NBR), 256>>>(p1w, p1b, out);
    mlp2_kernel<<<NBR * BATCH, 64>>>(p2w, p2b, out);
}